// round 9
// baseline (speedup 1.0000x reference)
#include <cuda_runtime.h>
#include <cuda_bf16.h>
#include <cstdint>

// Problem constants
#define BB   32
#define NN   1000
#define DIN  64
#define HH   128
#define AA   10
#define RB   (BB*NN)          // 32000 rows
#define MAXJ 128

// ======================= scratch (static device globals) ========================
__device__ float g_h  [RB*HH];
__device__ float g_t  [RB*HH];
__device__ float g_g1 [RB*3*HH];
__device__ float g_g2 [RB*3*HH];
__device__ int   g_adj[RB*MAXJ];
__device__ int   g_cnt[RB];
// fragment-packed weights: uint4 per (kstep, ntile, lane) = {bh0,bh1,bl0,bl1}
// count = (K/16) * (N/8) * 32
__device__ uint4 g_Benc[4*16*32];      // K=64,  N=128
__device__ uint4 g_Bo1 [8*16*32];      // K=128, N=128
__device__ uint4 g_Bo2 [8*16*32];
__device__ uint4 g_Bih [8*48*32];      // K=128, N=384
__device__ uint4 g_Bhh [8*48*32];
__device__ uint4 g_Bv1 [8*48*32];
__device__ uint4 g_Bv2 [8*48*32];
__device__ float g_bp1 [3*HH];
__device__ float g_bp2 [3*HH];

// ======================= helpers ================================================
__device__ __forceinline__ void bsplit(float v, uint16_t& h, uint16_t& l) {
    __nv_bfloat16 bh = __float2bfloat16(v);
    float fh = __bfloat162float(bh);
    __nv_bfloat16 bl = __float2bfloat16(v - fh);
    h = __bfloat16_as_ushort(bh);
    l = __bfloat16_as_ushort(bl);
}
__device__ __forceinline__ uint32_t pk(uint16_t lo, uint16_t hi) {
    return ((uint32_t)hi << 16) | lo;
}
#define MMA_BF16(d, a, b0, b1)                                                   \
    asm volatile("mma.sync.aligned.m16n8k16.row.col.f32.bf16.bf16.f32 "          \
                 "{%0,%1,%2,%3}, {%4,%5,%6,%7}, {%8,%9}, {%0,%1,%2,%3};"         \
                 : "+f"((d)[0]), "+f"((d)[1]), "+f"((d)[2]), "+f"((d)[3])        \
                 : "r"((a)[0]), "r"((a)[1]), "r"((a)[2]), "r"((a)[3]),           \
                   "r"(b0), "r"(b1))

// ======================= weight fragment packing ================================
// For mma m16n8k16 col-major B: b0 = {B[k0][n], B[k0+1][n]}, b1 = rows k0+8,k0+9,
// k0 = ks*16 + (lane&3)*2, n = ntile*8 + (lane>>2).
__global__ void pack_frag_kernel(const float* __restrict__ W, uint4* __restrict__ Bp,
                                 int N, int K, int transb) {
    int i = blockIdx.x * blockDim.x + threadIdx.x;
    int NT = N >> 3, KS = K >> 4;
    if (i >= KS * NT * 32) return;
    int lane = i & 31, rest = i >> 5;
    int ntg = rest % NT, ks = rest / NT;
    int n = ntg * 8 + (lane >> 2);
    int k0 = ks * 16 + (lane & 3) * 2;
    float v[4];
    #pragma unroll
    for (int j = 0; j < 4; ++j) {
        int k = k0 + (j >> 1) * 8 + (j & 1);
        v[j] = transb ? W[n * K + k] : W[k * N + n];
    }
    uint16_t h[4], l[4];
    #pragma unroll
    for (int j = 0; j < 4; ++j) bsplit(v[j], h[j], l[j]);
    Bp[i] = make_uint4(pk(h[0], h[1]), pk(h[2], h[3]), pk(l[0], l[1]), pk(l[2], l[3]));
}

__global__ void pack_vqk_frag_kernel(const float* __restrict__ Wv, const float* __restrict__ Wq,
                                     const float* __restrict__ Wk, const float* __restrict__ bv,
                                     const float* __restrict__ bq, const float* __restrict__ bk,
                                     uint4* __restrict__ Bp, float* __restrict__ bp) {
    int i = blockIdx.x * blockDim.x + threadIdx.x;
    const int NT = 48, KS = 8, K = 128;
    if (i < HH) { bp[i] = bv[i]; bp[128 + i] = bq[i]; bp[256 + i] = bk[i]; }
    if (i >= KS * NT * 32) return;
    int lane = i & 31, rest = i >> 5;
    int ntg = rest % NT, ks = rest / NT;
    int n = ntg * 8 + (lane >> 2);
    const float* W = (n < 128) ? Wv : (n < 256) ? Wq : Wk;
    int nn = n & 127;
    int k0 = ks * 16 + (lane & 3) * 2;
    float v[4];
    #pragma unroll
    for (int j = 0; j < 4; ++j) {
        int k = k0 + (j >> 1) * 8 + (j & 1);
        v[j] = W[k * K + nn];             // Wv/Wq/Wk are [K=128, N=128] row-major
    }
    uint16_t h[4], l[4];
    #pragma unroll
    for (int j = 0; j < 4; ++j) bsplit(v[j], h[j], l[j]);
    Bp[i] = make_uint4(pk(h[0], h[1]), pk(h[2], h[3]), pk(l[0], l[1]), pk(l[2], l[3]));
}

// ======================= bf16x2 tensor-core GEMM ================================
// C[32000, NTOT] = relu?(A[32000,K] x B + bias), B pre-packed fragments.
// CTA tile 64x128, grid (500, NTOT/128). 8 warps = 2m x 4n, warp tile 32x32.
// Dual accumulators: accH = hi*hi, accC = lo*hi + hi*lo (summed in epilogue)
// to break the 3-deep HMMA RAW chain per accumulator slot.
template<int K, bool RELU>
__global__ __launch_bounds__(256)
void mma_gemm_kernel(const float* __restrict__ A, const uint4* __restrict__ Bp,
                     const float* __restrict__ bias, float* __restrict__ C, int NTOT) {
    constexpr int KSTEPS = K / 16, KPAIRS = K / 2, F4R = K / 4;
    extern __shared__ uint32_t sA[];                  // Ah [64*KPAIRS] | Al [64*KPAIRS]
    uint32_t* Ah = sA;
    uint32_t* Al = sA + 64 * KPAIRS;
    const int tid = threadIdx.x, lane = tid & 31, wid = tid >> 5;
    const int mrow0 = blockIdx.x * 64, ncol0 = blockIdx.y * 128;

    // ---- convert A tile fp32 -> hi/lo bf16 pairs, XOR-swizzled ----
    #pragma unroll
    for (int c = 0; c < (64 * F4R) / 256; ++c) {
        int idx = tid + c * 256;
        int r = idx / F4R, q = idx % F4R;
        float4 v = *(const float4*)(A + (size_t)(mrow0 + r) * K + q * 4);
        uint16_t h0,l0,h1,l1,h2,l2,h3,l3;
        bsplit(v.x, h0, l0); bsplit(v.y, h1, l1);
        bsplit(v.z, h2, l2); bsplit(v.w, h3, l3);
        int p0 = q * 2, sw = (r & 7) << 2, base = r * KPAIRS;
        Ah[base + (p0 ^ sw)]       = pk(h0, h1);
        Ah[base + ((p0 + 1) ^ sw)] = pk(h2, h3);
        Al[base + (p0 ^ sw)]       = pk(l0, l1);
        Al[base + ((p0 + 1) ^ sw)] = pk(l2, l3);
    }
    __syncthreads();

    const int wm = wid & 1, wn = wid >> 1;
    const int g = lane >> 2, tg = lane & 3;
    const int NTtot = NTOT >> 3;
    const int ntbase = (ncol0 >> 3) + wn * 4;

    float accH[2][4][4], accC[2][4][4];
    #pragma unroll
    for (int mt = 0; mt < 2; ++mt)
        #pragma unroll
        for (int nt = 0; nt < 4; ++nt)
            #pragma unroll
            for (int j = 0; j < 4; ++j) { accH[mt][nt][j] = 0.f; accC[mt][nt][j] = 0.f; }

    #pragma unroll
    for (int ks = 0; ks < KSTEPS; ++ks) {
        uint32_t ah[2][4], al[2][4];
        #pragma unroll
        for (int mt = 0; mt < 2; ++mt) {
            int row = wm * 32 + mt * 16 + g;
            int sw = (row & 7) << 2;                  // (row+8)&7 == row&7
            int b0 = row * KPAIRS, b8 = (row + 8) * KPAIRS;
            int p0 = ks * 8 + tg;
            ah[mt][0] = Ah[b0 + (p0 ^ sw)];
            ah[mt][1] = Ah[b8 + (p0 ^ sw)];
            ah[mt][2] = Ah[b0 + ((p0 + 4) ^ sw)];
            ah[mt][3] = Ah[b8 + ((p0 + 4) ^ sw)];
            al[mt][0] = Al[b0 + (p0 ^ sw)];
            al[mt][1] = Al[b8 + (p0 ^ sw)];
            al[mt][2] = Al[b0 + ((p0 + 4) ^ sw)];
            al[mt][3] = Al[b8 + ((p0 + 4) ^ sw)];
        }
        // batch B fragment loads for all 4 n-tiles
        uint4 b[4];
        #pragma unroll
        for (int nt = 0; nt < 4; ++nt)
            b[nt] = Bp[(size_t)(ks * NTtot + ntbase + nt) * 32 + lane];

        // hi*hi wave (8 independent MMAs into accH)
        #pragma unroll
        for (int nt = 0; nt < 4; ++nt)
            #pragma unroll
            for (int mt = 0; mt < 2; ++mt)
                MMA_BF16(accH[mt][nt], ah[mt], b[nt].x, b[nt].y);
        // correction waves (into accC; at most 2-deep chain per slot)
        #pragma unroll
        for (int nt = 0; nt < 4; ++nt)
            #pragma unroll
            for (int mt = 0; mt < 2; ++mt)
                MMA_BF16(accC[mt][nt], al[mt], b[nt].x, b[nt].y);
        #pragma unroll
        for (int nt = 0; nt < 4; ++nt)
            #pragma unroll
            for (int mt = 0; mt < 2; ++mt)
                MMA_BF16(accC[mt][nt], ah[mt], b[nt].z, b[nt].w);
    }

    // ---- epilogue: accH + accC + bias (+relu) + store ----
    #pragma unroll
    for (int mt = 0; mt < 2; ++mt) {
        int row = mrow0 + wm * 32 + mt * 16 + g;
        #pragma unroll
        for (int nt = 0; nt < 4; ++nt) {
            int col = ncol0 + wn * 32 + nt * 8 + tg * 2;
            float b0 = bias[col], b1 = bias[col + 1];
            float2 v0 = make_float2(accH[mt][nt][0] + accC[mt][nt][0] + b0,
                                    accH[mt][nt][1] + accC[mt][nt][1] + b1);
            float2 v1 = make_float2(accH[mt][nt][2] + accC[mt][nt][2] + b0,
                                    accH[mt][nt][3] + accC[mt][nt][3] + b1);
            if (RELU) {
                v0.x = fmaxf(v0.x, 0.f); v0.y = fmaxf(v0.y, 0.f);
                v1.x = fmaxf(v1.x, 0.f); v1.y = fmaxf(v1.y, 0.f);
            }
            *(float2*)(C + (size_t)row * NTOT + col)       = v0;
            *(float2*)(C + (size_t)(row + 8) * NTOT + col) = v1;
        }
    }
}

// ======================= adjacency build ========================================
__global__ void build_adj_kernel(const float* __restrict__ mask) {
    int warp = (blockIdx.x * blockDim.x + threadIdx.x) >> 5;
    int lane = threadIdx.x & 31;
    if (warp >= RB) return;
    const float* row = mask + (size_t)warp * NN;
    int cnt = 0;
    for (int j0 = 0; j0 < NN; j0 += 32) {
        int j = j0 + lane;
        bool on = (j < NN) && (row[j] > 0.5f);
        unsigned bal = __ballot_sync(0xffffffffu, on);
        if (on) {
            int pos = cnt + __popc(bal & ((1u << lane) - 1u));
            if (pos < MAXJ) g_adj[warp * MAXJ + pos] = j;
        }
        cnt += __popc(bal);
    }
    if (lane == 0) g_cnt[warp] = min(cnt, MAXJ);
}

// ======================= sparse attention (warp/row, online softmax) ============
__global__ void spattn_kernel(const float* __restrict__ vqk, float* __restrict__ out) {
    int warp = (blockIdx.x * blockDim.x + threadIdx.x) >> 5;
    int lane = threadIdx.x & 31;
    if (warp >= RB) return;
    int base = (warp / NN) * NN;
    float4 q4 = *(const float4*)(vqk + (size_t)warp * 384 + 128 + lane * 4);
    int cnt = g_cnt[warp];
    const int* adj = g_adj + warp * MAXJ;
    float m = -3.4e38f, l = 0.f;
    float4 acc = make_float4(0.f, 0.f, 0.f, 0.f);
    for (int t = 0; t < cnt; ++t) {
        size_t j = (size_t)(base + adj[t]) * 384;
        float4 k4 = *(const float4*)(vqk + j + 256 + lane * 4);
        float p = q4.x*k4.x + q4.y*k4.y + q4.z*k4.z + q4.w*k4.w;
        #pragma unroll
        for (int o = 16; o > 0; o >>= 1) p += __shfl_xor_sync(0xffffffffu, p, o);
        float4 v4 = *(const float4*)(vqk + j + lane * 4);
        float nm = fmaxf(m, p);
        float sc = __expf(m - nm);
        float e  = __expf(p - nm);
        l = l * sc + e;
        acc.x = acc.x * sc + e * v4.x;
        acc.y = acc.y * sc + e * v4.y;
        acc.z = acc.z * sc + e * v4.z;
        acc.w = acc.w * sc + e * v4.w;
        m = nm;
    }
    float inv = 1.f / l;
    float4 o4 = make_float4(acc.x*inv, acc.y*inv, acc.z*inv, acc.w*inv);
    *(float4*)(out + (size_t)warp * HH + lane * 4) = o4;
}

// ======================= GRU gate fusion (float4) ===============================
__global__ void gru_gate_kernel(const float* __restrict__ g1, const float* __restrict__ g2,
                                const float* __restrict__ hin, float* __restrict__ hout) {
    int idx = blockIdx.x * blockDim.x + threadIdx.x;   // over RB*HH/4
    if (idx >= RB * HH / 4) return;
    int mrow = idx >> 5;            // 32 float4 per row
    int k4 = (idx & 31) << 2;
    size_t b = (size_t)mrow * (3 * HH) + k4;
    float4 xr = *(const float4*)(g1 + b);
    float4 hr = *(const float4*)(g2 + b);
    float4 xz = *(const float4*)(g1 + b + HH);
    float4 hz = *(const float4*)(g2 + b + HH);
    float4 xn = *(const float4*)(g1 + b + 2 * HH);
    float4 hn = *(const float4*)(g2 + b + 2 * HH);
    float4 hi = *(const float4*)(hin + (size_t)mrow * HH + k4);
    float4 o;
    {
        float r = 1.f / (1.f + __expf(-(xr.x + hr.x)));
        float z = 1.f / (1.f + __expf(-(xz.x + hz.x)));
        float n = tanhf(xn.x + r * hn.x);
        o.x = (1.f - z) * n + z * hi.x;
    }
    {
        float r = 1.f / (1.f + __expf(-(xr.y + hr.y)));
        float z = 1.f / (1.f + __expf(-(xz.y + hz.y)));
        float n = tanhf(xn.y + r * hn.y);
        o.y = (1.f - z) * n + z * hi.y;
    }
    {
        float r = 1.f / (1.f + __expf(-(xr.z + hr.z)));
        float z = 1.f / (1.f + __expf(-(xz.z + hz.z)));
        float n = tanhf(xn.z + r * hn.z);
        o.z = (1.f - z) * n + z * hi.z;
    }
    {
        float r = 1.f / (1.f + __expf(-(xr.w + hr.w)));
        float z = 1.f / (1.f + __expf(-(xz.w + hz.w)));
        float n = tanhf(xn.w + r * hn.w);
        o.w = (1.f - z) * n + z * hi.w;
    }
    *(float4*)(hout + (size_t)mrow * HH + k4) = o;
}

// ======================= FC head ================================================
__global__ void fc_kernel(const float* __restrict__ Hm, const float* __restrict__ W,
                          const float* __restrict__ bias, float* __restrict__ out) {
    __shared__ float Wt[AA * HH];
    __shared__ float bs[AA];
    int tid = threadIdx.x;
    for (int i = tid; i < AA * HH; i += blockDim.x) {
        int k = i / AA, a = i % AA;
        Wt[a * HH + k] = W[i];
    }
    if (tid < AA) bs[tid] = bias[tid];
    __syncthreads();
    int warp = (blockIdx.x * blockDim.x + tid) >> 5;
    int lane = tid & 31;
    if (warp >= RB) return;
    float4 h4 = *(const float4*)(Hm + (size_t)warp * HH + lane * 4);
    #pragma unroll
    for (int a = 0; a < AA; ++a) {
        float4 w4 = *(const float4*)(Wt + a * HH + lane * 4);
        float p = h4.x*w4.x + h4.y*w4.y + h4.z*w4.z + h4.w*w4.w;
        #pragma unroll
        for (int o = 16; o > 0; o >>= 1) p += __shfl_xor_sync(0xffffffffu, p, o);
        if (lane == 0) out[warp * AA + a] = p + bs[a];
    }
}

// ======================= launch =================================================
extern "C" void kernel_launch(void* const* d_in, const int* in_sizes, int n_in,
                              void* d_out, int out_size) {
    const float* x      = (const float*)d_in[0];
    const float* mask   = (const float*)d_in[1];
    const float* hidden = (const float*)d_in[2];
    const float* encW   = (const float*)d_in[3];
    const float* encb   = (const float*)d_in[4];
    const float* Wv1 = (const float*)d_in[5],  *bv1 = (const float*)d_in[6];
    const float* Wk1 = (const float*)d_in[7],  *bk1 = (const float*)d_in[8];
    const float* Wq1 = (const float*)d_in[9],  *bq1 = (const float*)d_in[10];
    const float* Wo1 = (const float*)d_in[11], *bo1 = (const float*)d_in[12];
    const float* Wv2 = (const float*)d_in[13], *bv2 = (const float*)d_in[14];
    const float* Wk2 = (const float*)d_in[15], *bk2 = (const float*)d_in[16];
    const float* Wq2 = (const float*)d_in[17], *bq2 = (const float*)d_in[18];
    const float* Wo2 = (const float*)d_in[19], *bo2 = (const float*)d_in[20];
    const float* Wih = (const float*)d_in[21], *bih = (const float*)d_in[22];
    const float* Whh = (const float*)d_in[23], *bhh = (const float*)d_in[24];
    const float* fcW = (const float*)d_in[25], *fcb = (const float*)d_in[26];

    float* out = (float*)d_out;
    float* qout = out;
    float* hout = out + (size_t)RB * AA;

    float *ph, *pt, *pg1, *pg2, *pbp1, *pbp2;
    uint4 *pBenc, *pBo1, *pBo2, *pBih, *pBhh, *pBv1, *pBv2;
    cudaGetSymbolAddress((void**)&ph,   g_h);
    cudaGetSymbolAddress((void**)&pt,   g_t);
    cudaGetSymbolAddress((void**)&pg1,  g_g1);
    cudaGetSymbolAddress((void**)&pg2,  g_g2);
    cudaGetSymbolAddress((void**)&pBenc, g_Benc);
    cudaGetSymbolAddress((void**)&pBo1,  g_Bo1);
    cudaGetSymbolAddress((void**)&pBo2,  g_Bo2);
    cudaGetSymbolAddress((void**)&pBih,  g_Bih);
    cudaGetSymbolAddress((void**)&pBhh,  g_Bhh);
    cudaGetSymbolAddress((void**)&pBv1,  g_Bv1);
    cudaGetSymbolAddress((void**)&pBv2,  g_Bv2);
    cudaGetSymbolAddress((void**)&pbp1,  g_bp1);
    cudaGetSymbolAddress((void**)&pbp2,  g_bp2);

    const int WB = 256;
    const int rowBlocks = RB / (WB / 32);     // 4000
    const int smemK128 = 64 * 64 * 4 * 2;     // 32 KB
    const int smemK64  = 64 * 32 * 4 * 2;     // 16 KB

    cudaFuncSetAttribute(mma_gemm_kernel<64,  true>,  cudaFuncAttributeMaxDynamicSharedMemorySize, smemK64);
    cudaFuncSetAttribute(mma_gemm_kernel<128, true>,  cudaFuncAttributeMaxDynamicSharedMemorySize, smemK128);
    cudaFuncSetAttribute(mma_gemm_kernel<128, false>, cudaFuncAttributeMaxDynamicSharedMemorySize, smemK128);

    // ---- weight fragment packing ----
    pack_frag_kernel<<<(4*16*32 + WB-1)/WB, WB>>>(encW, pBenc, 128, 64, 0);
    pack_frag_kernel<<<(8*16*32 + WB-1)/WB, WB>>>(Wo1,  pBo1,  128, 128, 0);
    pack_frag_kernel<<<(8*16*32 + WB-1)/WB, WB>>>(Wo2,  pBo2,  128, 128, 0);
    pack_frag_kernel<<<(8*48*32 + WB-1)/WB, WB>>>(Wih,  pBih,  384, 128, 1);
    pack_frag_kernel<<<(8*48*32 + WB-1)/WB, WB>>>(Whh,  pBhh,  384, 128, 1);
    pack_vqk_frag_kernel<<<(8*48*32 + WB-1)/WB, WB>>>(Wv1, Wq1, Wk1, bv1, bq1, bk1, pBv1, pbp1);
    pack_vqk_frag_kernel<<<(8*48*32 + WB-1)/WB, WB>>>(Wv2, Wq2, Wk2, bv2, bq2, bk2, pBv2, pbp2);
    build_adj_kernel<<<rowBlocks, WB>>>(mask);

    dim3 grid128(RB / 64, 1);    // (500,1)
    dim3 grid384(RB / 64, 3);    // (500,3)

    // encoder: h1 = relu(x @ encW + encb)
    mma_gemm_kernel<64, true><<<grid128, WB, smemK64>>>(x, pBenc, encb, ph, HH);

    // ---- attention layer 1 ----
    mma_gemm_kernel<128, true><<<grid384, WB, smemK128>>>(ph, pBv1, pbp1, pg1, 3*HH);
    spattn_kernel<<<rowBlocks, WB>>>(pg1, pt);
    mma_gemm_kernel<128, true><<<grid128, WB, smemK128>>>(pt, pBo1, bo1, ph, HH);

    // ---- attention layer 2 ----
    mma_gemm_kernel<128, true><<<grid384, WB, smemK128>>>(ph, pBv2, pbp2, pg1, 3*HH);
    spattn_kernel<<<rowBlocks, WB>>>(pg1, pt);
    mma_gemm_kernel<128, true><<<grid128, WB, smemK128>>>(pt, pBo2, bo2, ph, HH);

    // ---- GRU ----
    mma_gemm_kernel<128, false><<<grid384, WB, smemK128>>>(ph, pBih, bih, pg1, 3*HH);
    mma_gemm_kernel<128, false><<<grid384, WB, smemK128>>>(hidden, pBhh, bhh, pg2, 3*HH);
    gru_gate_kernel<<<(RB * HH / 4 + WB - 1) / WB, WB>>>(pg1, pg2, hidden, hout);

    // ---- head ----
    fc_kernel<<<rowBlocks, WB>>>(hout, fcW, fcb, qout);
    (void)in_sizes; (void)n_in; (void)out_size;
}

// round 10
// speedup vs baseline: 1.0839x; 1.0839x over previous
#include <cuda_runtime.h>
#include <cuda_bf16.h>
#include <cstdint>

// Problem constants
#define BB   32
#define NN   1000
#define DIN  64
#define HH   128
#define AA   10
#define RB   (BB*NN)          // 32000 rows
#define MAXJ 128

// ======================= scratch (static device globals) ========================
__device__ float g_h  [RB*HH];
__device__ float g_t  [RB*HH];
__device__ float g_g1 [RB*3*HH];
__device__ float g_g2 [RB*3*HH];
__device__ int   g_adj[RB*MAXJ];
__device__ int   g_cnt[RB];
// fragment-packed weights: uint4 per (kstep, ntile, lane) = {bh0,bh1,bl0,bl1}
__device__ uint4 g_Benc[4*16*32];      // K=64,  N=128
__device__ uint4 g_Bo1 [8*16*32];      // K=128, N=128
__device__ uint4 g_Bo2 [8*16*32];
__device__ uint4 g_Bih [8*48*32];      // K=128, N=384
__device__ uint4 g_Bhh [8*48*32];
__device__ uint4 g_Bv1 [8*48*32];
__device__ uint4 g_Bv2 [8*48*32];
__device__ float g_bp1 [3*HH];
__device__ float g_bp2 [3*HH];

// ======================= helpers ================================================
__device__ __forceinline__ void bsplit(float v, uint16_t& h, uint16_t& l) {
    __nv_bfloat16 bh = __float2bfloat16(v);
    float fh = __bfloat162float(bh);
    __nv_bfloat16 bl = __float2bfloat16(v - fh);
    h = __bfloat16_as_ushort(bh);
    l = __bfloat16_as_ushort(bl);
}
__device__ __forceinline__ uint32_t pk(uint16_t lo, uint16_t hi) {
    return ((uint32_t)hi << 16) | lo;
}
// {trunc_bf16(a) in low half, trunc_bf16(b) in high half}
__device__ __forceinline__ uint32_t prmt_hi(uint32_t a, uint32_t b) {
    uint32_t r;
    asm("prmt.b32 %0, %1, %2, 0x7632;" : "=r"(r) : "r"(a), "r"(b));
    return r;
}
// {bf16(lo_val) in low half, bf16(hi_val) in high half}
__device__ __forceinline__ uint32_t cvt_bf16x2(float hi_val, float lo_val) {
    uint32_t r;
    asm("cvt.rn.bf16x2.f32 %0, %1, %2;" : "=r"(r) : "f"(hi_val), "f"(lo_val));
    return r;
}
#define MMA_BF16(d, a, b0, b1)                                                   \
    asm volatile("mma.sync.aligned.m16n8k16.row.col.f32.bf16.bf16.f32 "          \
                 "{%0,%1,%2,%3}, {%4,%5,%6,%7}, {%8,%9}, {%0,%1,%2,%3};"         \
                 : "+f"((d)[0]), "+f"((d)[1]), "+f"((d)[2]), "+f"((d)[3])        \
                 : "r"((a)[0]), "r"((a)[1]), "r"((a)[2]), "r"((a)[3]),           \
                   "r"(b0), "r"(b1))

// ======================= merged weight packing ==================================
// Per-element fetchers differ per job; fragment layout identical (see R8 notes):
// b0 = {B[k0][n], B[k0+1][n]}, b1 = rows k0+8,k0+9; k0 = ks*16+(lane&3)*2,
// n = ntile*8 + (lane>>2).
__device__ __forceinline__ void pack_one(const float* __restrict__ W,
                                         uint4* __restrict__ Bp,
                                         int N, int K, int transb, int i) {
    int NT = N >> 3;
    int lane = i & 31, rest = i >> 5;
    int ntg = rest % NT, ks = rest / NT;
    int n = ntg * 8 + (lane >> 2);
    int k0 = ks * 16 + (lane & 3) * 2;
    float v[4];
    #pragma unroll
    for (int j = 0; j < 4; ++j) {
        int k = k0 + (j >> 1) * 8 + (j & 1);
        v[j] = transb ? W[n * K + k] : W[k * N + n];
    }
    uint16_t h[4], l[4];
    #pragma unroll
    for (int j = 0; j < 4; ++j) bsplit(v[j], h[j], l[j]);
    Bp[i] = make_uint4(pk(h[0], h[1]), pk(h[2], h[3]), pk(l[0], l[1]), pk(l[2], l[3]));
}
__device__ __forceinline__ void pack_one_vqk(const float* __restrict__ Wv,
                                             const float* __restrict__ Wq,
                                             const float* __restrict__ Wk,
                                             uint4* __restrict__ Bp, int i) {
    const int NT = 48, K = 128;
    int lane = i & 31, rest = i >> 5;
    int ntg = rest % NT, ks = rest / NT;
    int n = ntg * 8 + (lane >> 2);
    const float* W = (n < 128) ? Wv : (n < 256) ? Wq : Wk;
    int nn = n & 127;
    int k0 = ks * 16 + (lane & 3) * 2;
    float v[4];
    #pragma unroll
    for (int j = 0; j < 4; ++j) {
        int k = k0 + (j >> 1) * 8 + (j & 1);
        v[j] = W[k * K + nn];
    }
    uint16_t h[4], l[4];
    #pragma unroll
    for (int j = 0; j < 4; ++j) bsplit(v[j], h[j], l[j]);
    Bp[i] = make_uint4(pk(h[0], h[1]), pk(h[2], h[3]), pk(l[0], l[1]), pk(l[2], l[3]));
}

__global__ void pack_all_kernel(
    const float* encW, const float* Wo1, const float* Wo2,
    const float* Wih,  const float* Whh,
    const float* Wv1, const float* Wq1, const float* Wk1,
    const float* Wv2, const float* Wq2, const float* Wk2,
    const float* bv1, const float* bq1, const float* bk1,
    const float* bv2, const float* bq2, const float* bk2,
    uint4* Benc, uint4* Bo1, uint4* Bo2, uint4* Bih, uint4* Bhh,
    uint4* Bv1, uint4* Bv2, float* bp1, float* bp2) {
    int i = blockIdx.x * blockDim.x + threadIdx.x;
    if      (i < 2048)  pack_one(encW, Benc, 128, 64, 0, i);
    else if (i < 6144)  pack_one(Wo1, Bo1, 128, 128, 0, i - 2048);
    else if (i < 10240) pack_one(Wo2, Bo2, 128, 128, 0, i - 6144);
    else if (i < 22528) pack_one(Wih, Bih, 384, 128, 1, i - 10240);
    else if (i < 34816) pack_one(Whh, Bhh, 384, 128, 1, i - 22528);
    else if (i < 47104) pack_one_vqk(Wv1, Wq1, Wk1, Bv1, i - 34816);
    else if (i < 59392) pack_one_vqk(Wv2, Wq2, Wk2, Bv2, i - 47104);
    else if (i < 59520) { int j = i - 59392; bp1[j] = bv1[j]; bp1[128+j] = bq1[j]; bp1[256+j] = bk1[j]; }
    else if (i < 59648) { int j = i - 59520; bp2[j] = bv2[j]; bp2[128+j] = bq2[j]; bp2[256+j] = bk2[j]; }
}

// ======================= bf16x2 tensor-core GEMM (R8 mainloop) ==================
// C[32000, NTOT] = relu?(A[32000,K] x B + bias).
// CTA tile 64x128, grid (500, NTOT/128). 8 warps = 2m x 4n, warp tile 32x32.
template<int K, bool RELU>
__global__ __launch_bounds__(256)
void mma_gemm_kernel(const float* __restrict__ A, const uint4* __restrict__ Bp,
                     const float* __restrict__ bias, float* __restrict__ C, int NTOT) {
    constexpr int KSTEPS = K / 16, KPAIRS = K / 2, F4R = K / 4;
    extern __shared__ uint32_t sA[];                  // Ah [64*KPAIRS] | Al [64*KPAIRS]
    uint32_t* Ah = sA;
    uint32_t* Al = sA + 64 * KPAIRS;
    const int tid = threadIdx.x, lane = tid & 31, wid = tid >> 5;
    const int mrow0 = blockIdx.x * 64, ncol0 = blockIdx.y * 128;

    // ---- convert A tile fp32 -> hi(trunc)/lo bf16 pairs, XOR-swizzled ----
    #pragma unroll
    for (int c = 0; c < (64 * F4R) / 256; ++c) {
        int idx = tid + c * 256;
        int r = idx / F4R, q = idx % F4R;
        float4 v = *(const float4*)(A + (size_t)(mrow0 + r) * K + q * 4);
        uint32_t ax = __float_as_uint(v.x), ay = __float_as_uint(v.y);
        uint32_t az = __float_as_uint(v.z), aw = __float_as_uint(v.w);
        uint32_t h01 = prmt_hi(ax, ay);
        uint32_t h23 = prmt_hi(az, aw);
        float lx = v.x - __uint_as_float(ax & 0xFFFF0000u);
        float ly = v.y - __uint_as_float(ay & 0xFFFF0000u);
        float lz = v.z - __uint_as_float(az & 0xFFFF0000u);
        float lw = v.w - __uint_as_float(aw & 0xFFFF0000u);
        uint32_t l01 = cvt_bf16x2(ly, lx);    // low half = lx
        uint32_t l23 = cvt_bf16x2(lw, lz);
        int p0 = q * 2, sw = (r & 7) << 2, base = r * KPAIRS;
        Ah[base + (p0 ^ sw)]       = h01;
        Ah[base + ((p0 + 1) ^ sw)] = h23;
        Al[base + (p0 ^ sw)]       = l01;
        Al[base + ((p0 + 1) ^ sw)] = l23;
    }
    __syncthreads();

    const int wm = wid & 1, wn = wid >> 1;
    const int g = lane >> 2, tg = lane & 3;
    const int NTtot = NTOT >> 3;
    const int ntbase = (ncol0 >> 3) + wn * 4;

    float acc[2][4][4];
    #pragma unroll
    for (int mt = 0; mt < 2; ++mt)
        #pragma unroll
        for (int nt = 0; nt < 4; ++nt)
            #pragma unroll
            for (int j = 0; j < 4; ++j) acc[mt][nt][j] = 0.f;

    #pragma unroll
    for (int ks = 0; ks < KSTEPS; ++ks) {
        uint32_t ah[2][4], al[2][4];
        #pragma unroll
        for (int mt = 0; mt < 2; ++mt) {
            int row = wm * 32 + mt * 16 + g;
            int sw = (row & 7) << 2;                  // (row+8)&7 == row&7
            int b0 = row * KPAIRS, b8 = (row + 8) * KPAIRS;
            int p0 = ks * 8 + tg;
            ah[mt][0] = Ah[b0 + (p0 ^ sw)];
            ah[mt][1] = Ah[b8 + (p0 ^ sw)];
            ah[mt][2] = Ah[b0 + ((p0 + 4) ^ sw)];
            ah[mt][3] = Ah[b8 + ((p0 + 4) ^ sw)];
            al[mt][0] = Al[b0 + (p0 ^ sw)];
            al[mt][1] = Al[b8 + (p0 ^ sw)];
            al[mt][2] = Al[b0 + ((p0 + 4) ^ sw)];
            al[mt][3] = Al[b8 + ((p0 + 4) ^ sw)];
        }
        #pragma unroll
        for (int nt = 0; nt < 4; ++nt) {
            uint4 b = Bp[(size_t)(ks * NTtot + ntbase + nt) * 32 + lane];
            #pragma unroll
            for (int mt = 0; mt < 2; ++mt) {
                MMA_BF16(acc[mt][nt], ah[mt], b.x, b.y);   // hi*hi
                MMA_BF16(acc[mt][nt], al[mt], b.x, b.y);   // lo*hi
                MMA_BF16(acc[mt][nt], ah[mt], b.z, b.w);   // hi*lo
            }
        }
    }

    // ---- epilogue: bias (+relu) + store ----
    #pragma unroll
    for (int mt = 0; mt < 2; ++mt) {
        int row = mrow0 + wm * 32 + mt * 16 + g;
        #pragma unroll
        for (int nt = 0; nt < 4; ++nt) {
            int col = ncol0 + wn * 32 + nt * 8 + tg * 2;
            float b0 = bias[col], b1 = bias[col + 1];
            float2 v0 = make_float2(acc[mt][nt][0] + b0, acc[mt][nt][1] + b1);
            float2 v1 = make_float2(acc[mt][nt][2] + b0, acc[mt][nt][3] + b1);
            if (RELU) {
                v0.x = fmaxf(v0.x, 0.f); v0.y = fmaxf(v0.y, 0.f);
                v1.x = fmaxf(v1.x, 0.f); v1.y = fmaxf(v1.y, 0.f);
            }
            *(float2*)(C + (size_t)row * NTOT + col)       = v0;
            *(float2*)(C + (size_t)(row + 8) * NTOT + col) = v1;
        }
    }
}

// ======================= adjacency build ========================================
__global__ void build_adj_kernel(const float* __restrict__ mask) {
    int warp = (blockIdx.x * blockDim.x + threadIdx.x) >> 5;
    int lane = threadIdx.x & 31;
    if (warp >= RB) return;
    const float* row = mask + (size_t)warp * NN;
    int cnt = 0;
    for (int j0 = 0; j0 < NN; j0 += 32) {
        int j = j0 + lane;
        bool on = (j < NN) && (row[j] > 0.5f);
        unsigned bal = __ballot_sync(0xffffffffu, on);
        if (on) {
            int pos = cnt + __popc(bal & ((1u << lane) - 1u));
            if (pos < MAXJ) g_adj[warp * MAXJ + pos] = j;
        }
        cnt += __popc(bal);
    }
    if (lane == 0) g_cnt[warp] = min(cnt, MAXJ);
}

// ======================= sparse attention (warp/row, online softmax) ============
__global__ void spattn_kernel(const float* __restrict__ vqk, float* __restrict__ out) {
    int warp = (blockIdx.x * blockDim.x + threadIdx.x) >> 5;
    int lane = threadIdx.x & 31;
    if (warp >= RB) return;
    int base = (warp / NN) * NN;
    float4 q4 = *(const float4*)(vqk + (size_t)warp * 384 + 128 + lane * 4);
    int cnt = g_cnt[warp];
    const int* adj = g_adj + warp * MAXJ;
    float m = -3.4e38f, l = 0.f;
    float4 acc = make_float4(0.f, 0.f, 0.f, 0.f);
    for (int t = 0; t < cnt; ++t) {
        size_t j = (size_t)(base + adj[t]) * 384;
        float4 k4 = *(const float4*)(vqk + j + 256 + lane * 4);
        float p = q4.x*k4.x + q4.y*k4.y + q4.z*k4.z + q4.w*k4.w;
        #pragma unroll
        for (int o = 16; o > 0; o >>= 1) p += __shfl_xor_sync(0xffffffffu, p, o);
        float4 v4 = *(const float4*)(vqk + j + lane * 4);
        float nm = fmaxf(m, p);
        float sc = __expf(m - nm);
        float e  = __expf(p - nm);
        l = l * sc + e;
        acc.x = acc.x * sc + e * v4.x;
        acc.y = acc.y * sc + e * v4.y;
        acc.z = acc.z * sc + e * v4.z;
        acc.w = acc.w * sc + e * v4.w;
        m = nm;
    }
    float inv = 1.f / l;
    float4 o4 = make_float4(acc.x*inv, acc.y*inv, acc.z*inv, acc.w*inv);
    *(float4*)(out + (size_t)warp * HH + lane * 4) = o4;
}

// ======================= fused GRU gate + FC head (warp/row) ====================
__global__ void gru_fc_kernel(const float* __restrict__ g1, const float* __restrict__ g2,
                              const float* __restrict__ hin, const float* __restrict__ fcW,
                              const float* __restrict__ fcb,
                              float* __restrict__ hout, float* __restrict__ qout) {
    __shared__ float Wt[AA * HH];   // transposed: Wt[a*128 + k]
    __shared__ float bs[AA];
    int tid = threadIdx.x;
    for (int i = tid; i < AA * HH; i += blockDim.x) {
        int k = i / AA, a = i % AA;
        Wt[a * HH + k] = fcW[i];
    }
    if (tid < AA) bs[tid] = fcb[tid];
    __syncthreads();
    int warp = (blockIdx.x * blockDim.x + tid) >> 5;
    int lane = tid & 31;
    if (warp >= RB) return;
    size_t b = (size_t)warp * (3 * HH) + lane * 4;
    float4 xr = *(const float4*)(g1 + b);
    float4 hr = *(const float4*)(g2 + b);
    float4 xz = *(const float4*)(g1 + b + HH);
    float4 hz = *(const float4*)(g2 + b + HH);
    float4 xn = *(const float4*)(g1 + b + 2 * HH);
    float4 hn = *(const float4*)(g2 + b + 2 * HH);
    float4 hi4 = *(const float4*)(hin + (size_t)warp * HH + lane * 4);
    float4 o;
    {
        float r = 1.f / (1.f + __expf(-(xr.x + hr.x)));
        float z = 1.f / (1.f + __expf(-(xz.x + hz.x)));
        float n = tanhf(xn.x + r * hn.x);
        o.x = (1.f - z) * n + z * hi4.x;
    }
    {
        float r = 1.f / (1.f + __expf(-(xr.y + hr.y)));
        float z = 1.f / (1.f + __expf(-(xz.y + hz.y)));
        float n = tanhf(xn.y + r * hn.y);
        o.y = (1.f - z) * n + z * hi4.y;
    }
    {
        float r = 1.f / (1.f + __expf(-(xr.z + hr.z)));
        float z = 1.f / (1.f + __expf(-(xz.z + hz.z)));
        float n = tanhf(xn.z + r * hn.z);
        o.z = (1.f - z) * n + z * hi4.z;
    }
    {
        float r = 1.f / (1.f + __expf(-(xr.w + hr.w)));
        float z = 1.f / (1.f + __expf(-(xz.w + hz.w)));
        float n = tanhf(xn.w + r * hn.w);
        o.w = (1.f - z) * n + z * hi4.w;
    }
    *(float4*)(hout + (size_t)warp * HH + lane * 4) = o;
    #pragma unroll
    for (int a = 0; a < AA; ++a) {
        float4 w4 = *(const float4*)(Wt + a * HH + lane * 4);
        float p = o.x*w4.x + o.y*w4.y + o.z*w4.z + o.w*w4.w;
        #pragma unroll
        for (int off = 16; off > 0; off >>= 1) p += __shfl_xor_sync(0xffffffffu, p, off);
        if (lane == 0) qout[warp * AA + a] = p + bs[a];
    }
}

// ======================= launch =================================================
extern "C" void kernel_launch(void* const* d_in, const int* in_sizes, int n_in,
                              void* d_out, int out_size) {
    const float* x      = (const float*)d_in[0];
    const float* mask   = (const float*)d_in[1];
    const float* hidden = (const float*)d_in[2];
    const float* encW   = (const float*)d_in[3];
    const float* encb   = (const float*)d_in[4];
    const float* Wv1 = (const float*)d_in[5],  *bv1 = (const float*)d_in[6];
    const float* Wk1 = (const float*)d_in[7],  *bk1 = (const float*)d_in[8];
    const float* Wq1 = (const float*)d_in[9],  *bq1 = (const float*)d_in[10];
    const float* Wo1 = (const float*)d_in[11], *bo1 = (const float*)d_in[12];
    const float* Wv2 = (const float*)d_in[13], *bv2 = (const float*)d_in[14];
    const float* Wk2 = (const float*)d_in[15], *bk2 = (const float*)d_in[16];
    const float* Wq2 = (const float*)d_in[17], *bq2 = (const float*)d_in[18];
    const float* Wo2 = (const float*)d_in[19], *bo2 = (const float*)d_in[20];
    const float* Wih = (const float*)d_in[21], *bih = (const float*)d_in[22];
    const float* Whh = (const float*)d_in[23], *bhh = (const float*)d_in[24];
    const float* fcW = (const float*)d_in[25], *fcb = (const float*)d_in[26];

    float* out = (float*)d_out;
    float* qout = out;
    float* hout = out + (size_t)RB * AA;

    float *ph, *pt, *pg1, *pg2, *pbp1, *pbp2;
    uint4 *pBenc, *pBo1, *pBo2, *pBih, *pBhh, *pBv1, *pBv2;
    cudaGetSymbolAddress((void**)&ph,   g_h);
    cudaGetSymbolAddress((void**)&pt,   g_t);
    cudaGetSymbolAddress((void**)&pg1,  g_g1);
    cudaGetSymbolAddress((void**)&pg2,  g_g2);
    cudaGetSymbolAddress((void**)&pBenc, g_Benc);
    cudaGetSymbolAddress((void**)&pBo1,  g_Bo1);
    cudaGetSymbolAddress((void**)&pBo2,  g_Bo2);
    cudaGetSymbolAddress((void**)&pBih,  g_Bih);
    cudaGetSymbolAddress((void**)&pBhh,  g_Bhh);
    cudaGetSymbolAddress((void**)&pBv1,  g_Bv1);
    cudaGetSymbolAddress((void**)&pBv2,  g_Bv2);
    cudaGetSymbolAddress((void**)&pbp1,  g_bp1);
    cudaGetSymbolAddress((void**)&pbp2,  g_bp2);

    const int WB = 256;
    const int rowBlocks = RB / (WB / 32);     // 4000
    const int smemK128 = 64 * 64 * 4 * 2;     // 32 KB
    const int smemK64  = 64 * 32 * 4 * 2;     // 16 KB

    cudaFuncSetAttribute(mma_gemm_kernel<64,  true>,  cudaFuncAttributeMaxDynamicSharedMemorySize, smemK64);
    cudaFuncSetAttribute(mma_gemm_kernel<128, true>,  cudaFuncAttributeMaxDynamicSharedMemorySize, smemK128);
    cudaFuncSetAttribute(mma_gemm_kernel<128, false>, cudaFuncAttributeMaxDynamicSharedMemorySize, smemK128);

    // ---- merged weight packing (single launch) + adjacency ----
    pack_all_kernel<<<(59648 + WB - 1) / WB, WB>>>(
        encW, Wo1, Wo2, Wih, Whh,
        Wv1, Wq1, Wk1, Wv2, Wq2, Wk2,
        bv1, bq1, bk1, bv2, bq2, bk2,
        pBenc, pBo1, pBo2, pBih, pBhh, pBv1, pBv2, pbp1, pbp2);
    build_adj_kernel<<<rowBlocks, WB>>>(mask);

    dim3 grid128(RB / 64, 1);    // (500,1)
    dim3 grid384(RB / 64, 3);    // (500,3)

    // encoder: h1 = relu(x @ encW + encb)
    mma_gemm_kernel<64, true><<<grid128, WB, smemK64>>>(x, pBenc, encb, ph, HH);

    // ---- attention layer 1 ----
    mma_gemm_kernel<128, true><<<grid384, WB, smemK128>>>(ph, pBv1, pbp1, pg1, 3*HH);
    spattn_kernel<<<rowBlocks, WB>>>(pg1, pt);
    mma_gemm_kernel<128, true><<<grid128, WB, smemK128>>>(pt, pBo1, bo1, ph, HH);

    // ---- attention layer 2 ----
    mma_gemm_kernel<128, true><<<grid384, WB, smemK128>>>(ph, pBv2, pbp2, pg1, 3*HH);
    spattn_kernel<<<rowBlocks, WB>>>(pg1, pt);
    mma_gemm_kernel<128, true><<<grid128, WB, smemK128>>>(pt, pBo2, bo2, ph, HH);

    // ---- GRU GEMMs + fused gate/head ----
    mma_gemm_kernel<128, false><<<grid384, WB, smemK128>>>(ph, pBih, bih, pg1, 3*HH);
    mma_gemm_kernel<128, false><<<grid384, WB, smemK128>>>(hidden, pBhh, bhh, pg2, 3*HH);
    gru_fc_kernel<<<rowBlocks, WB>>>(pg1, pg2, hidden, fcW, fcb, hout, qout);

    (void)in_sizes; (void)n_in; (void)out_size;
}

// round 12
// speedup vs baseline: 1.1960x; 1.1034x over previous
#include <cuda_runtime.h>
#include <cuda_bf16.h>
#include <cstdint>

// Problem constants
#define BB   32
#define NN   1000
#define DIN  64
#define HH   128
#define AA   10
#define RB   (BB*NN)          // 32000 rows
#define MAXJ 128

// ======================= scratch (static device globals) ========================
__device__ float g_h  [RB*HH];
__device__ float g_t  [RB*HH];
__device__ float g_g1 [RB*3*HH];
__device__ float g_g2 [RB*3*HH];
__device__ int   g_adj[RB*MAXJ];
__device__ int   g_cnt[RB];
// fragment-packed weights: uint4 per (kstep, ntile, lane) = {bh0,bh1,bl0,bl1}
__device__ uint4 g_Benc[4*16*32];      // K=64,  N=128
__device__ uint4 g_Bo1 [8*16*32];      // K=128, N=128
__device__ uint4 g_Bo2 [8*16*32];
__device__ uint4 g_Bih [8*48*32];      // K=128, N=384
__device__ uint4 g_Bhh [8*48*32];
__device__ uint4 g_Bv1 [8*48*32];
__device__ uint4 g_Bv2 [8*48*32];
__device__ float g_bp1 [3*HH];
__device__ float g_bp2 [3*HH];

// ======================= helpers ================================================
__device__ __forceinline__ uint32_t smem_u32(const void* p) {
    uint32_t a;
    asm("{ .reg .u64 t; cvta.to.shared.u64 t, %1; cvt.u32.u64 %0, t; }" : "=r"(a) : "l"(p));
    return a;
}
__device__ __forceinline__ void bsplit(float v, uint16_t& h, uint16_t& l) {
    __nv_bfloat16 bh = __float2bfloat16(v);
    float fh = __bfloat162float(bh);
    __nv_bfloat16 bl = __float2bfloat16(v - fh);
    h = __bfloat16_as_ushort(bh);
    l = __bfloat16_as_ushort(bl);
}
__device__ __forceinline__ uint32_t pk(uint16_t lo, uint16_t hi) {
    return ((uint32_t)hi << 16) | lo;
}
// {trunc_bf16(a) in low half, trunc_bf16(b) in high half}
__device__ __forceinline__ uint32_t prmt_hi(uint32_t a, uint32_t b) {
    uint32_t r;
    asm("prmt.b32 %0, %1, %2, 0x7632;" : "=r"(r) : "r"(a), "r"(b));
    return r;
}
// {bf16(lo_val) in low half, bf16(hi_val) in high half}
__device__ __forceinline__ uint32_t cvt_bf16x2(float hi_val, float lo_val) {
    uint32_t r;
    asm("cvt.rn.bf16x2.f32 %0, %1, %2;" : "=r"(r) : "f"(hi_val), "f"(lo_val));
    return r;
}
#define MMA_BF16(d, a, b0, b1)                                                   \
    asm volatile("mma.sync.aligned.m16n8k16.row.col.f32.bf16.bf16.f32 "          \
                 "{%0,%1,%2,%3}, {%4,%5,%6,%7}, {%8,%9}, {%0,%1,%2,%3};"         \
                 : "+f"((d)[0]), "+f"((d)[1]), "+f"((d)[2]), "+f"((d)[3])        \
                 : "r"((a)[0]), "r"((a)[1]), "r"((a)[2]), "r"((a)[3]),           \
                   "r"(b0), "r"(b1))
#define LDSM_X4(r, addr)                                                         \
    asm volatile("ldmatrix.sync.aligned.m8n8.x4.shared.b16 {%0,%1,%2,%3}, [%4];" \
                 : "=r"((r)[0]), "=r"((r)[1]), "=r"((r)[2]), "=r"((r)[3])        \
                 : "r"(addr))

// ======================= merged weight packing ==================================
// b0 = {B[k0][n], B[k0+1][n]}, b1 = rows k0+8,k0+9; k0 = ks*16+(lane&3)*2,
// n = ntile*8 + (lane>>2).
__device__ __forceinline__ void pack_one(const float* __restrict__ W,
                                         uint4* __restrict__ Bp,
                                         int N, int K, int transb, int i) {
    int NT = N >> 3;
    int lane = i & 31, rest = i >> 5;
    int ntg = rest % NT, ks = rest / NT;
    int n = ntg * 8 + (lane >> 2);
    int k0 = ks * 16 + (lane & 3) * 2;
    float v[4];
    #pragma unroll
    for (int j = 0; j < 4; ++j) {
        int k = k0 + (j >> 1) * 8 + (j & 1);
        v[j] = transb ? W[n * K + k] : W[k * N + n];
    }
    uint16_t h[4], l[4];
    #pragma unroll
    for (int j = 0; j < 4; ++j) bsplit(v[j], h[j], l[j]);
    Bp[i] = make_uint4(pk(h[0], h[1]), pk(h[2], h[3]), pk(l[0], l[1]), pk(l[2], l[3]));
}
__device__ __forceinline__ void pack_one_vqk(const float* __restrict__ Wv,
                                             const float* __restrict__ Wq,
                                             const float* __restrict__ Wk,
                                             uint4* __restrict__ Bp, int i) {
    const int NT = 48, K = 128;
    int lane = i & 31, rest = i >> 5;
    int ntg = rest % NT, ks = rest / NT;
    int n = ntg * 8 + (lane >> 2);
    const float* W = (n < 128) ? Wv : (n < 256) ? Wq : Wk;
    int nn = n & 127;
    int k0 = ks * 16 + (lane & 3) * 2;
    float v[4];
    #pragma unroll
    for (int j = 0; j < 4; ++j) {
        int k = k0 + (j >> 1) * 8 + (j & 1);
        v[j] = W[k * K + nn];
    }
    uint16_t h[4], l[4];
    #pragma unroll
    for (int j = 0; j < 4; ++j) bsplit(v[j], h[j], l[j]);
    Bp[i] = make_uint4(pk(h[0], h[1]), pk(h[2], h[3]), pk(l[0], l[1]), pk(l[2], l[3]));
}

__global__ void pack_all_kernel(
    const float* encW, const float* Wo1, const float* Wo2,
    const float* Wih,  const float* Whh,
    const float* Wv1, const float* Wq1, const float* Wk1,
    const float* Wv2, const float* Wq2, const float* Wk2,
    const float* bv1, const float* bq1, const float* bk1,
    const float* bv2, const float* bq2, const float* bk2,
    uint4* Benc, uint4* Bo1, uint4* Bo2, uint4* Bih, uint4* Bhh,
    uint4* Bv1, uint4* Bv2, float* bp1, float* bp2) {
    int i = blockIdx.x * blockDim.x + threadIdx.x;
    if      (i < 2048)  pack_one(encW, Benc, 128, 64, 0, i);
    else if (i < 6144)  pack_one(Wo1, Bo1, 128, 128, 0, i - 2048);
    else if (i < 10240) pack_one(Wo2, Bo2, 128, 128, 0, i - 6144);
    else if (i < 22528) pack_one(Wih, Bih, 384, 128, 1, i - 10240);
    else if (i < 34816) pack_one(Whh, Bhh, 384, 128, 1, i - 22528);
    else if (i < 47104) pack_one_vqk(Wv1, Wq1, Wk1, Bv1, i - 34816);
    else if (i < 59392) pack_one_vqk(Wv2, Wq2, Wk2, Bv2, i - 47104);
    else if (i < 59520) { int j = i - 59392; bp1[j] = bv1[j]; bp1[128+j] = bq1[j]; bp1[256+j] = bk1[j]; }
    else if (i < 59648) { int j = i - 59520; bp2[j] = bv2[j]; bp2[128+j] = bq2[j]; bp2[256+j] = bk2[j]; }
}

// ======================= bf16x2 tensor-core GEMM (ldmatrix A) ===================
// C[32000, NTOT] = relu?(A[32000,K] x B + bias).
// CTA tile 64x128, grid (500, NTOT/128). 8 warps = 2m x 4n, warp tile 32x32.
template<int K, bool RELU>
__global__ __launch_bounds__(256)
void mma_gemm_kernel(const float* __restrict__ A, const uint4* __restrict__ Bp,
                     const float* __restrict__ bias, float* __restrict__ C, int NTOT) {
    constexpr int KSTEPS = K / 16, KPAIRS = K / 2, F4R = K / 4;
    extern __shared__ uint32_t sA[];                  // Ah [64*KPAIRS] | Al [64*KPAIRS]
    uint32_t* Ah = sA;
    uint32_t* Al = sA + 64 * KPAIRS;
    const int tid = threadIdx.x, lane = tid & 31, wid = tid >> 5;
    const int mrow0 = blockIdx.x * 64, ncol0 = blockIdx.y * 128;

    // ---- convert A tile fp32 -> hi(trunc)/lo bf16 pairs, XOR-swizzled ----
    #pragma unroll
    for (int c = 0; c < (64 * F4R) / 256; ++c) {
        int idx = tid + c * 256;
        int r = idx / F4R, q = idx % F4R;
        float4 v = *(const float4*)(A + (size_t)(mrow0 + r) * K + q * 4);
        uint32_t ax = __float_as_uint(v.x), ay = __float_as_uint(v.y);
        uint32_t az = __float_as_uint(v.z), aw = __float_as_uint(v.w);
        uint32_t h01 = prmt_hi(ax, ay);
        uint32_t h23 = prmt_hi(az, aw);
        float lx = v.x - __uint_as_float(ax & 0xFFFF0000u);
        float ly = v.y - __uint_as_float(ay & 0xFFFF0000u);
        float lz = v.z - __uint_as_float(az & 0xFFFF0000u);
        float lw = v.w - __uint_as_float(aw & 0xFFFF0000u);
        uint32_t l01 = cvt_bf16x2(ly, lx);    // low half = lx
        uint32_t l23 = cvt_bf16x2(lw, lz);
        int p0 = q * 2, sw = (r & 7) << 2, base = r * KPAIRS;
        Ah[base + (p0 ^ sw)]       = h01;
        Ah[base + ((p0 + 1) ^ sw)] = h23;
        Al[base + (p0 ^ sw)]       = l01;
        Al[base + ((p0 + 1) ^ sw)] = l23;
    }
    __syncthreads();

    const int wm = wid & 1, wn = wid >> 1;
    const int g = lane >> 2, tg = lane & 3;
    const int NTtot = NTOT >> 3;
    const int ntbase = (ncol0 >> 3) + wn * 4;

    // ldmatrix lane mapping: lanes 0-7 -> rows 0-7 khalf0, 8-15 -> rows 8-15 khalf0,
    // 16-23 -> rows 0-7 khalf1, 24-31 -> rows 8-15 khalf1. Result m0..m3 = a0..a3.
    const int row_in = (lane & 7) | (((lane >> 3) & 1) << 3);
    const int c4 = ((lane >> 4) & 1) << 2;      // pair offset for k-half
    const int swl = (row_in & 7) << 2;          // mt adds 16 rows: (row&7) unchanged
    uint32_t abase[2], lbase[2];
    #pragma unroll
    for (int mt = 0; mt < 2; ++mt) {
        int row = wm * 32 + mt * 16 + row_in;
        abase[mt] = smem_u32(Ah + row * KPAIRS);
        lbase[mt] = smem_u32(Al + row * KPAIRS);
    }

    float acc[2][4][4];
    #pragma unroll
    for (int mt = 0; mt < 2; ++mt)
        #pragma unroll
        for (int nt = 0; nt < 4; ++nt)
            #pragma unroll
            for (int j = 0; j < 4; ++j) acc[mt][nt][j] = 0.f;

    #pragma unroll
    for (int ks = 0; ks < KSTEPS; ++ks) {
        uint32_t poff = (uint32_t)((((ks * 8) | c4) ^ swl) << 2);   // byte offset
        uint32_t ah[2][4], al[2][4];
        LDSM_X4(ah[0], abase[0] + poff);
        LDSM_X4(ah[1], abase[1] + poff);
        LDSM_X4(al[0], lbase[0] + poff);
        LDSM_X4(al[1], lbase[1] + poff);
        #pragma unroll
        for (int nt = 0; nt < 4; ++nt) {
            uint4 b = Bp[(size_t)(ks * NTtot + ntbase + nt) * 32 + lane];
            #pragma unroll
            for (int mt = 0; mt < 2; ++mt) {
                MMA_BF16(acc[mt][nt], ah[mt], b.x, b.y);   // hi*hi
                MMA_BF16(acc[mt][nt], al[mt], b.x, b.y);   // lo*hi
                MMA_BF16(acc[mt][nt], ah[mt], b.z, b.w);   // hi*lo
            }
        }
    }

    // ---- epilogue: bias (+relu) + store ----
    #pragma unroll
    for (int mt = 0; mt < 2; ++mt) {
        int row = mrow0 + wm * 32 + mt * 16 + g;
        #pragma unroll
        for (int nt = 0; nt < 4; ++nt) {
            int col = ncol0 + wn * 32 + nt * 8 + tg * 2;
            float b0 = bias[col], b1 = bias[col + 1];
            float2 v0 = make_float2(acc[mt][nt][0] + b0, acc[mt][nt][1] + b1);
            float2 v1 = make_float2(acc[mt][nt][2] + b0, acc[mt][nt][3] + b1);
            if (RELU) {
                v0.x = fmaxf(v0.x, 0.f); v0.y = fmaxf(v0.y, 0.f);
                v1.x = fmaxf(v1.x, 0.f); v1.y = fmaxf(v1.y, 0.f);
            }
            *(float2*)(C + (size_t)row * NTOT + col)       = v0;
            *(float2*)(C + (size_t)(row + 8) * NTOT + col) = v1;
        }
    }
}

// ======================= adjacency build ========================================
__global__ void build_adj_kernel(const float* __restrict__ mask) {
    int warp = (blockIdx.x * blockDim.x + threadIdx.x) >> 5;
    int lane = threadIdx.x & 31;
    if (warp >= RB) return;
    const float* row = mask + (size_t)warp * NN;
    int cnt = 0;
    for (int j0 = 0; j0 < NN; j0 += 32) {
        int j = j0 + lane;
        bool on = (j < NN) && (row[j] > 0.5f);
        unsigned bal = __ballot_sync(0xffffffffu, on);
        if (on) {
            int pos = cnt + __popc(bal & ((1u << lane) - 1u));
            if (pos < MAXJ) g_adj[warp * MAXJ + pos] = j;
        }
        cnt += __popc(bal);
    }
    if (lane == 0) g_cnt[warp] = min(cnt, MAXJ);
}

// ======================= sparse attention (warp/row, online softmax) ============
__global__ void spattn_kernel(const float* __restrict__ vqk, float* __restrict__ out) {
    int warp = (blockIdx.x * blockDim.x + threadIdx.x) >> 5;
    int lane = threadIdx.x & 31;
    if (warp >= RB) return;
    int base = (warp / NN) * NN;
    float4 q4 = *(const float4*)(vqk + (size_t)warp * 384 + 128 + lane * 4);
    int cnt = g_cnt[warp];
    const int* adj = g_adj + warp * MAXJ;
    float m = -3.4e38f, l = 0.f;
    float4 acc = make_float4(0.f, 0.f, 0.f, 0.f);
    for (int t = 0; t < cnt; ++t) {
        size_t j = (size_t)(base + adj[t]) * 384;
        float4 k4 = *(const float4*)(vqk + j + 256 + lane * 4);
        float p = q4.x*k4.x + q4.y*k4.y + q4.z*k4.z + q4.w*k4.w;
        #pragma unroll
        for (int o = 16; o > 0; o >>= 1) p += __shfl_xor_sync(0xffffffffu, p, o);
        float4 v4 = *(const float4*)(vqk + j + lane * 4);
        float nm = fmaxf(m, p);
        float sc = __expf(m - nm);
        float e  = __expf(p - nm);
        l = l * sc + e;
        acc.x = acc.x * sc + e * v4.x;
        acc.y = acc.y * sc + e * v4.y;
        acc.z = acc.z * sc + e * v4.z;
        acc.w = acc.w * sc + e * v4.w;
        m = nm;
    }
    float inv = 1.f / l;
    float4 o4 = make_float4(acc.x*inv, acc.y*inv, acc.z*inv, acc.w*inv);
    *(float4*)(out + (size_t)warp * HH + lane * 4) = o4;
}

// ======================= fused GRU gate + FC head (warp/row) ====================
__global__ void gru_fc_kernel(const float* __restrict__ g1, const float* __restrict__ g2,
                              const float* __restrict__ hin, const float* __restrict__ fcW,
                              const float* __restrict__ fcb,
                              float* __restrict__ hout, float* __restrict__ qout) {
    __shared__ float Wt[AA * HH];   // transposed: Wt[a*128 + k]
    __shared__ float bs[AA];
    int tid = threadIdx.x;
    for (int i = tid; i < AA * HH; i += blockDim.x) {
        int k = i / AA, a = i % AA;
        Wt[a * HH + k] = fcW[i];
    }
    if (tid < AA) bs[tid] = fcb[tid];
    __syncthreads();
    int warp = (blockIdx.x * blockDim.x + tid) >> 5;
    int lane = tid & 31;
    if (warp >= RB) return;
    size_t b = (size_t)warp * (3 * HH) + lane * 4;
    float4 xr = *(const float4*)(g1 + b);
    float4 hr = *(const float4*)(g2 + b);
    float4 xz = *(const float4*)(g1 + b + HH);
    float4 hz = *(const float4*)(g2 + b + HH);
    float4 xn = *(const float4*)(g1 + b + 2 * HH);
    float4 hn = *(const float4*)(g2 + b + 2 * HH);
    float4 hi4 = *(const float4*)(hin + (size_t)warp * HH + lane * 4);
    float4 o;
    {
        float r = 1.f / (1.f + __expf(-(xr.x + hr.x)));
        float z = 1.f / (1.f + __expf(-(xz.x + hz.x)));
        float n = tanhf(xn.x + r * hn.x);
        o.x = (1.f - z) * n + z * hi4.x;
    }
    {
        float r = 1.f / (1.f + __expf(-(xr.y + hr.y)));
        float z = 1.f / (1.f + __expf(-(xz.y + hz.y)));
        float n = tanhf(xn.y + r * hn.y);
        o.y = (1.f - z) * n + z * hi4.y;
    }
    {
        float r = 1.f / (1.f + __expf(-(xr.z + hr.z)));
        float z = 1.f / (1.f + __expf(-(xz.z + hz.z)));
        float n = tanhf(xn.z + r * hn.z);
        o.z = (1.f - z) * n + z * hi4.z;
    }
    {
        float r = 1.f / (1.f + __expf(-(xr.w + hr.w)));
        float z = 1.f / (1.f + __expf(-(xz.w + hz.w)));
        float n = tanhf(xn.w + r * hn.w);
        o.w = (1.f - z) * n + z * hi4.w;
    }
    *(float4*)(hout + (size_t)warp * HH + lane * 4) = o;
    #pragma unroll
    for (int a = 0; a < AA; ++a) {
        float4 w4 = *(const float4*)(Wt + a * HH + lane * 4);
        float p = o.x*w4.x + o.y*w4.y + o.z*w4.z + o.w*w4.w;
        #pragma unroll
        for (int off = 16; off > 0; off >>= 1) p += __shfl_xor_sync(0xffffffffu, p, off);
        if (lane == 0) qout[warp * AA + a] = p + bs[a];
    }
}

// ======================= launch =================================================
extern "C" void kernel_launch(void* const* d_in, const int* in_sizes, int n_in,
                              void* d_out, int out_size) {
    const float* x      = (const float*)d_in[0];
    const float* mask   = (const float*)d_in[1];
    const float* hidden = (const float*)d_in[2];
    const float* encW   = (const float*)d_in[3];
    const float* encb   = (const float*)d_in[4];
    const float* Wv1 = (const float*)d_in[5],  *bv1 = (const float*)d_in[6];
    const float* Wk1 = (const float*)d_in[7],  *bk1 = (const float*)d_in[8];
    const float* Wq1 = (const float*)d_in[9],  *bq1 = (const float*)d_in[10];
    const float* Wo1 = (const float*)d_in[11], *bo1 = (const float*)d_in[12];
    const float* Wv2 = (const float*)d_in[13], *bv2 = (const float*)d_in[14];
    const float* Wk2 = (const float*)d_in[15], *bk2 = (const float*)d_in[16];
    const float* Wq2 = (const float*)d_in[17], *bq2 = (const float*)d_in[18];
    const float* Wo2 = (const float*)d_in[19], *bo2 = (const float*)d_in[20];
    const float* Wih = (const float*)d_in[21], *bih = (const float*)d_in[22];
    const float* Whh = (const float*)d_in[23], *bhh = (const float*)d_in[24];
    const float* fcW = (const float*)d_in[25], *fcb = (const float*)d_in[26];

    float* out = (float*)d_out;
    float* qout = out;
    float* hout = out + (size_t)RB * AA;

    float *ph, *pt, *pg1, *pg2, *pbp1, *pbp2;
    uint4 *pBenc, *pBo1, *pBo2, *pBih, *pBhh, *pBv1, *pBv2;
    cudaGetSymbolAddress((void**)&ph,   g_h);
    cudaGetSymbolAddress((void**)&pt,   g_t);
    cudaGetSymbolAddress((void**)&pg1,  g_g1);
    cudaGetSymbolAddress((void**)&pg2,  g_g2);
    cudaGetSymbolAddress((void**)&pBenc, g_Benc);
    cudaGetSymbolAddress((void**)&pBo1,  g_Bo1);
    cudaGetSymbolAddress((void**)&pBo2,  g_Bo2);
    cudaGetSymbolAddress((void**)&pBih,  g_Bih);
    cudaGetSymbolAddress((void**)&pBhh,  g_Bhh);
    cudaGetSymbolAddress((void**)&pBv1,  g_Bv1);
    cudaGetSymbolAddress((void**)&pBv2,  g_Bv2);
    cudaGetSymbolAddress((void**)&pbp1,  g_bp1);
    cudaGetSymbolAddress((void**)&pbp2,  g_bp2);

    const int WB = 256;
    const int rowBlocks = RB / (WB / 32);     // 4000
    const int smemK128 = 64 * 64 * 4 * 2;     // 32 KB
    const int smemK64  = 64 * 32 * 4 * 2;     // 16 KB

    cudaFuncSetAttribute(mma_gemm_kernel<64,  true>,  cudaFuncAttributeMaxDynamicSharedMemorySize, smemK64);
    cudaFuncSetAttribute(mma_gemm_kernel<128, true>,  cudaFuncAttributeMaxDynamicSharedMemorySize, smemK128);
    cudaFuncSetAttribute(mma_gemm_kernel<128, false>, cudaFuncAttributeMaxDynamicSharedMemorySize, smemK128);

    // ---- merged weight packing (single launch) + adjacency ----
    pack_all_kernel<<<(59648 + WB - 1) / WB, WB>>>(
        encW, Wo1, Wo2, Wih, Whh,
        Wv1, Wq1, Wk1, Wv2, Wq2, Wk2,
        bv1, bq1, bk1, bv2, bq2, bk2,
        pBenc, pBo1, pBo2, pBih, pBhh, pBv1, pBv2, pbp1, pbp2);
    build_adj_kernel<<<rowBlocks, WB>>>(mask);

    dim3 grid128(RB / 64, 1);    // (500,1)
    dim3 grid384(RB / 64, 3);    // (500,3)

    // encoder: h1 = relu(x @ encW + encb)
    mma_gemm_kernel<64, true><<<grid128, WB, smemK64>>>(x, pBenc, encb, ph, HH);

    // ---- attention layer 1 ----
    mma_gemm_kernel<128, true><<<grid384, WB, smemK128>>>(ph, pBv1, pbp1, pg1, 3*HH);
    spattn_kernel<<<rowBlocks, WB>>>(pg1, pt);
    mma_gemm_kernel<128, true><<<grid128, WB, smemK128>>>(pt, pBo1, bo1, ph, HH);

    // ---- attention layer 2 ----
    mma_gemm_kernel<128, true><<<grid384, WB, smemK128>>>(ph, pBv2, pbp2, pg1, 3*HH);
    spattn_kernel<<<rowBlocks, WB>>>(pg1, pt);
    mma_gemm_kernel<128, true><<<grid128, WB, smemK128>>>(pt, pBo2, bo2, ph, HH);

    // ---- GRU GEMMs + fused gate/head ----
    mma_gemm_kernel<128, false><<<grid384, WB, smemK128>>>(ph, pBih, bih, pg1, 3*HH);
    mma_gemm_kernel<128, false><<<grid384, WB, smemK128>>>(hidden, pBhh, bhh, pg2, 3*HH);
    gru_fc_kernel<<<rowBlocks, WB>>>(pg1, pg2, hidden, fcW, fcb, hout, qout);

    (void)in_sizes; (void)n_in; (void)out_size;
}

// round 13
// speedup vs baseline: 1.2291x; 1.0277x over previous
#include <cuda_runtime.h>
#include <cuda_bf16.h>
#include <cstdint>

// Problem constants
#define BB   32
#define NN   1000
#define DIN  64
#define HH   128
#define AA   10
#define RB   (BB*NN)          // 32000 rows
#define MAXJ 128

// ======================= scratch (static device globals) ========================
__device__ float g_h  [RB*HH];
__device__ float g_t  [RB*HH];
__device__ float g_g1 [RB*3*HH];
__device__ float g_g2 [RB*3*HH];
__device__ int   g_adj[RB*MAXJ];
__device__ int   g_cnt[RB];
// fragment-packed weights: uint4 per (kstep, ntile, lane) = {bh0,bh1,bl0,bl1}
__device__ uint4 g_Benc[4*16*32];      // K=64,  N=128
__device__ uint4 g_Bo1 [8*16*32];      // K=128, N=128
__device__ uint4 g_Bo2 [8*16*32];
__device__ uint4 g_Bih [8*48*32];      // K=128, N=384
__device__ uint4 g_Bhh [8*48*32];
__device__ uint4 g_Bv1 [8*48*32];
__device__ uint4 g_Bv2 [8*48*32];
__device__ float g_bp1 [3*HH];
__device__ float g_bp2 [3*HH];

// ======================= helpers ================================================
__device__ __forceinline__ uint32_t smem_u32(const void* p) {
    uint32_t a;
    asm("{ .reg .u64 t; cvta.to.shared.u64 t, %1; cvt.u32.u64 %0, t; }" : "=r"(a) : "l"(p));
    return a;
}
__device__ __forceinline__ void bsplit(float v, uint16_t& h, uint16_t& l) {
    __nv_bfloat16 bh = __float2bfloat16(v);
    float fh = __bfloat162float(bh);
    __nv_bfloat16 bl = __float2bfloat16(v - fh);
    h = __bfloat16_as_ushort(bh);
    l = __bfloat16_as_ushort(bl);
}
__device__ __forceinline__ uint32_t pk(uint16_t lo, uint16_t hi) {
    return ((uint32_t)hi << 16) | lo;
}
// {trunc_bf16(a) in low half, trunc_bf16(b) in high half}
__device__ __forceinline__ uint32_t prmt_hi(uint32_t a, uint32_t b) {
    uint32_t r;
    asm("prmt.b32 %0, %1, %2, 0x7632;" : "=r"(r) : "r"(a), "r"(b));
    return r;
}
// {bf16(lo_val) in low half, bf16(hi_val) in high half}
__device__ __forceinline__ uint32_t cvt_bf16x2(float hi_val, float lo_val) {
    uint32_t r;
    asm("cvt.rn.bf16x2.f32 %0, %1, %2;" : "=r"(r) : "f"(hi_val), "f"(lo_val));
    return r;
}
#define MMA_BF16(d, a, b0, b1)                                                   \
    asm volatile("mma.sync.aligned.m16n8k16.row.col.f32.bf16.bf16.f32 "          \
                 "{%0,%1,%2,%3}, {%4,%5,%6,%7}, {%8,%9}, {%0,%1,%2,%3};"         \
                 : "+f"((d)[0]), "+f"((d)[1]), "+f"((d)[2]), "+f"((d)[3])        \
                 : "r"((a)[0]), "r"((a)[1]), "r"((a)[2]), "r"((a)[3]),           \
                   "r"(b0), "r"(b1))
#define LDSM_X4(r, addr)                                                         \
    asm volatile("ldmatrix.sync.aligned.m8n8.x4.shared.b16 {%0,%1,%2,%3}, [%4];" \
                 : "=r"((r)[0]), "=r"((r)[1]), "=r"((r)[2]), "=r"((r)[3])        \
                 : "r"(addr))

// ======================= merged weight packing ==================================
// b0 = {B[k0][n], B[k0+1][n]}, b1 = rows k0+8,k0+9; k0 = ks*16+(lane&3)*2,
// n = ntile*8 + (lane>>2).
__device__ __forceinline__ void pack_one(const float* __restrict__ W,
                                         uint4* __restrict__ Bp,
                                         int N, int K, int transb, int i) {
    int NT = N >> 3;
    int lane = i & 31, rest = i >> 5;
    int ntg = rest % NT, ks = rest / NT;
    int n = ntg * 8 + (lane >> 2);
    int k0 = ks * 16 + (lane & 3) * 2;
    float v[4];
    #pragma unroll
    for (int j = 0; j < 4; ++j) {
        int k = k0 + (j >> 1) * 8 + (j & 1);
        v[j] = transb ? W[n * K + k] : W[k * N + n];
    }
    uint16_t h[4], l[4];
    #pragma unroll
    for (int j = 0; j < 4; ++j) bsplit(v[j], h[j], l[j]);
    Bp[i] = make_uint4(pk(h[0], h[1]), pk(h[2], h[3]), pk(l[0], l[1]), pk(l[2], l[3]));
}
__device__ __forceinline__ void pack_one_vqk(const float* __restrict__ Wv,
                                             const float* __restrict__ Wq,
                                             const float* __restrict__ Wk,
                                             uint4* __restrict__ Bp, int i) {
    const int NT = 48, K = 128;
    int lane = i & 31, rest = i >> 5;
    int ntg = rest % NT, ks = rest / NT;
    int n = ntg * 8 + (lane >> 2);
    const float* W = (n < 128) ? Wv : (n < 256) ? Wq : Wk;
    int nn = n & 127;
    int k0 = ks * 16 + (lane & 3) * 2;
    float v[4];
    #pragma unroll
    for (int j = 0; j < 4; ++j) {
        int k = k0 + (j >> 1) * 8 + (j & 1);
        v[j] = W[k * K + nn];
    }
    uint16_t h[4], l[4];
    #pragma unroll
    for (int j = 0; j < 4; ++j) bsplit(v[j], h[j], l[j]);
    Bp[i] = make_uint4(pk(h[0], h[1]), pk(h[2], h[3]), pk(l[0], l[1]), pk(l[2], l[3]));
}

__global__ void pack_all_kernel(
    const float* encW, const float* Wo1, const float* Wo2,
    const float* Wih,  const float* Whh,
    const float* Wv1, const float* Wq1, const float* Wk1,
    const float* Wv2, const float* Wq2, const float* Wk2,
    const float* bv1, const float* bq1, const float* bk1,
    const float* bv2, const float* bq2, const float* bk2,
    uint4* Benc, uint4* Bo1, uint4* Bo2, uint4* Bih, uint4* Bhh,
    uint4* Bv1, uint4* Bv2, float* bp1, float* bp2) {
    int i = blockIdx.x * blockDim.x + threadIdx.x;
    if      (i < 2048)  pack_one(encW, Benc, 128, 64, 0, i);
    else if (i < 6144)  pack_one(Wo1, Bo1, 128, 128, 0, i - 2048);
    else if (i < 10240) pack_one(Wo2, Bo2, 128, 128, 0, i - 6144);
    else if (i < 22528) pack_one(Wih, Bih, 384, 128, 1, i - 10240);
    else if (i < 34816) pack_one(Whh, Bhh, 384, 128, 1, i - 22528);
    else if (i < 47104) pack_one_vqk(Wv1, Wq1, Wk1, Bv1, i - 34816);
    else if (i < 59392) pack_one_vqk(Wv2, Wq2, Wk2, Bv2, i - 47104);
    else if (i < 59520) { int j = i - 59392; bp1[j] = bv1[j]; bp1[128+j] = bq1[j]; bp1[256+j] = bk1[j]; }
    else if (i < 59648) { int j = i - 59520; bp2[j] = bv2[j]; bp2[128+j] = bq2[j]; bp2[256+j] = bk2[j]; }
}

// ======================= bf16x2 tensor-core GEMM core ===========================
// C[32000, NTOT] = relu?(A[32000,K] x B + bias).
// CTA tile 64x128, 8 warps = 2m x 4n, warp tile 32x32, ldmatrix A fragments.
template<int K, bool RELU>
__device__ __forceinline__ void gemm_body(const float* __restrict__ A,
                                          const uint4* __restrict__ Bp,
                                          const float* __restrict__ bias,
                                          float* __restrict__ C,
                                          int NTOT, int bx, int by) {
    constexpr int KSTEPS = K / 16, KPAIRS = K / 2, F4R = K / 4;
    extern __shared__ uint32_t sA[];                  // Ah [64*KPAIRS] | Al [64*KPAIRS]
    uint32_t* Ah = sA;
    uint32_t* Al = sA + 64 * KPAIRS;
    const int tid = threadIdx.x, lane = tid & 31, wid = tid >> 5;
    const int mrow0 = bx * 64, ncol0 = by * 128;

    // ---- convert A tile fp32 -> hi(trunc)/lo bf16 pairs, XOR-swizzled ----
    #pragma unroll
    for (int c = 0; c < (64 * F4R) / 256; ++c) {
        int idx = tid + c * 256;
        int r = idx / F4R, q = idx % F4R;
        float4 v = *(const float4*)(A + (size_t)(mrow0 + r) * K + q * 4);
        uint32_t ax = __float_as_uint(v.x), ay = __float_as_uint(v.y);
        uint32_t az = __float_as_uint(v.z), aw = __float_as_uint(v.w);
        uint32_t h01 = prmt_hi(ax, ay);
        uint32_t h23 = prmt_hi(az, aw);
        float lx = v.x - __uint_as_float(ax & 0xFFFF0000u);
        float ly = v.y - __uint_as_float(ay & 0xFFFF0000u);
        float lz = v.z - __uint_as_float(az & 0xFFFF0000u);
        float lw = v.w - __uint_as_float(aw & 0xFFFF0000u);
        uint32_t l01 = cvt_bf16x2(ly, lx);    // low half = lx
        uint32_t l23 = cvt_bf16x2(lw, lz);
        int p0 = q * 2, sw = (r & 7) << 2, base = r * KPAIRS;
        Ah[base + (p0 ^ sw)]       = h01;
        Ah[base + ((p0 + 1) ^ sw)] = h23;
        Al[base + (p0 ^ sw)]       = l01;
        Al[base + ((p0 + 1) ^ sw)] = l23;
    }
    __syncthreads();

    const int wm = wid & 1, wn = wid >> 1;
    const int g = lane >> 2, tg = lane & 3;
    const int NTtot = NTOT >> 3;
    const int ntbase = (ncol0 >> 3) + wn * 4;

    // ldmatrix lane mapping: lanes 0-7 -> rows 0-7 khalf0, 8-15 -> rows 8-15 khalf0,
    // 16-23 -> rows 0-7 khalf1, 24-31 -> rows 8-15 khalf1. Result m0..m3 = a0..a3.
    const int row_in = (lane & 7) | (((lane >> 3) & 1) << 3);
    const int c4 = ((lane >> 4) & 1) << 2;      // pair offset for k-half
    const int swl = (row_in & 7) << 2;          // mt adds 16 rows: (row&7) unchanged
    uint32_t abase[2], lbase[2];
    #pragma unroll
    for (int mt = 0; mt < 2; ++mt) {
        int row = wm * 32 + mt * 16 + row_in;
        abase[mt] = smem_u32(Ah + row * KPAIRS);
        lbase[mt] = smem_u32(Al + row * KPAIRS);
    }

    float acc[2][4][4];
    #pragma unroll
    for (int mt = 0; mt < 2; ++mt)
        #pragma unroll
        for (int nt = 0; nt < 4; ++nt)
            #pragma unroll
            for (int j = 0; j < 4; ++j) acc[mt][nt][j] = 0.f;

    #pragma unroll
    for (int ks = 0; ks < KSTEPS; ++ks) {
        uint32_t poff = (uint32_t)((((ks * 8) | c4) ^ swl) << 2);   // byte offset
        uint32_t ah[2][4], al[2][4];
        LDSM_X4(ah[0], abase[0] + poff);
        LDSM_X4(ah[1], abase[1] + poff);
        LDSM_X4(al[0], lbase[0] + poff);
        LDSM_X4(al[1], lbase[1] + poff);
        #pragma unroll
        for (int nt = 0; nt < 4; ++nt) {
            uint4 b = Bp[(size_t)(ks * NTtot + ntbase + nt) * 32 + lane];
            #pragma unroll
            for (int mt = 0; mt < 2; ++mt) {
                MMA_BF16(acc[mt][nt], ah[mt], b.x, b.y);   // hi*hi
                MMA_BF16(acc[mt][nt], al[mt], b.x, b.y);   // lo*hi
                MMA_BF16(acc[mt][nt], ah[mt], b.z, b.w);   // hi*lo
            }
        }
    }

    // ---- epilogue: bias (+relu) + store ----
    #pragma unroll
    for (int mt = 0; mt < 2; ++mt) {
        int row = mrow0 + wm * 32 + mt * 16 + g;
        #pragma unroll
        for (int nt = 0; nt < 4; ++nt) {
            int col = ncol0 + wn * 32 + nt * 8 + tg * 2;
            float b0 = bias[col], b1 = bias[col + 1];
            float2 v0 = make_float2(acc[mt][nt][0] + b0, acc[mt][nt][1] + b1);
            float2 v1 = make_float2(acc[mt][nt][2] + b0, acc[mt][nt][3] + b1);
            if (RELU) {
                v0.x = fmaxf(v0.x, 0.f); v0.y = fmaxf(v0.y, 0.f);
                v1.x = fmaxf(v1.x, 0.f); v1.y = fmaxf(v1.y, 0.f);
            }
            *(float2*)(C + (size_t)row * NTOT + col)       = v0;
            *(float2*)(C + (size_t)(row + 8) * NTOT + col) = v1;
        }
    }
}

template<int K, bool RELU>
__global__ __launch_bounds__(256, 3)
void mma_gemm_kernel(const float* __restrict__ A, const uint4* __restrict__ Bp,
                     const float* __restrict__ bias, float* __restrict__ C, int NTOT) {
    gemm_body<K, RELU>(A, Bp, bias, C, NTOT, blockIdx.x, blockIdx.y);
}

// Dual GEMM: two independent same-shape GEMMs in one launch (kills one tail).
template<int K, bool RELU>
__global__ __launch_bounds__(256, 3)
void mma_gemm_dual_kernel(const float* __restrict__ A0, const uint4* __restrict__ B0,
                          const float* __restrict__ c0, float* __restrict__ C0,
                          const float* __restrict__ A1, const uint4* __restrict__ B1,
                          const float* __restrict__ c1, float* __restrict__ C1,
                          int NTOT, int split) {
    int bx = blockIdx.x;
    if (bx < split) gemm_body<K, RELU>(A0, B0, c0, C0, NTOT, bx, blockIdx.y);
    else            gemm_body<K, RELU>(A1, B1, c1, C1, NTOT, bx - split, blockIdx.y);
}

// ======================= adjacency build ========================================
__global__ void build_adj_kernel(const float* __restrict__ mask) {
    int warp = (blockIdx.x * blockDim.x + threadIdx.x) >> 5;
    int lane = threadIdx.x & 31;
    if (warp >= RB) return;
    const float* row = mask + (size_t)warp * NN;
    int cnt = 0;
    for (int j0 = 0; j0 < NN; j0 += 32) {
        int j = j0 + lane;
        bool on = (j < NN) && (row[j] > 0.5f);
        unsigned bal = __ballot_sync(0xffffffffu, on);
        if (on) {
            int pos = cnt + __popc(bal & ((1u << lane) - 1u));
            if (pos < MAXJ) g_adj[warp * MAXJ + pos] = j;
        }
        cnt += __popc(bal);
    }
    if (lane == 0) g_cnt[warp] = min(cnt, MAXJ);
}

// ======================= sparse attention (warp/row, online softmax) ============
__global__ void spattn_kernel(const float* __restrict__ vqk, float* __restrict__ out) {
    int warp = (blockIdx.x * blockDim.x + threadIdx.x) >> 5;
    int lane = threadIdx.x & 31;
    if (warp >= RB) return;
    int base = (warp / NN) * NN;
    float4 q4 = *(const float4*)(vqk + (size_t)warp * 384 + 128 + lane * 4);
    int cnt = g_cnt[warp];
    const int* adj = g_adj + warp * MAXJ;
    float m = -3.4e38f, l = 0.f;
    float4 acc = make_float4(0.f, 0.f, 0.f, 0.f);
    for (int t = 0; t < cnt; ++t) {
        size_t j = (size_t)(base + adj[t]) * 384;
        float4 k4 = *(const float4*)(vqk + j + 256 + lane * 4);
        float p = q4.x*k4.x + q4.y*k4.y + q4.z*k4.z + q4.w*k4.w;
        #pragma unroll
        for (int o = 16; o > 0; o >>= 1) p += __shfl_xor_sync(0xffffffffu, p, o);
        float4 v4 = *(const float4*)(vqk + j + lane * 4);
        float nm = fmaxf(m, p);
        float sc = __expf(m - nm);
        float e  = __expf(p - nm);
        l = l * sc + e;
        acc.x = acc.x * sc + e * v4.x;
        acc.y = acc.y * sc + e * v4.y;
        acc.z = acc.z * sc + e * v4.z;
        acc.w = acc.w * sc + e * v4.w;
        m = nm;
    }
    float inv = 1.f / l;
    float4 o4 = make_float4(acc.x*inv, acc.y*inv, acc.z*inv, acc.w*inv);
    *(float4*)(out + (size_t)warp * HH + lane * 4) = o4;
}

// ======================= fused GRU gate + FC head (warp/row) ====================
__global__ void gru_fc_kernel(const float* __restrict__ g1, const float* __restrict__ g2,
                              const float* __restrict__ hin, const float* __restrict__ fcW,
                              const float* __restrict__ fcb,
                              float* __restrict__ hout, float* __restrict__ qout) {
    __shared__ float Wt[AA * HH];   // transposed: Wt[a*128 + k]
    __shared__ float bs[AA];
    int tid = threadIdx.x;
    for (int i = tid; i < AA * HH; i += blockDim.x) {
        int k = i / AA, a = i % AA;
        Wt[a * HH + k] = fcW[i];
    }
    if (tid < AA) bs[tid] = fcb[tid];
    __syncthreads();
    int warp = (blockIdx.x * blockDim.x + tid) >> 5;
    int lane = tid & 31;
    if (warp >= RB) return;
    size_t b = (size_t)warp * (3 * HH) + lane * 4;
    float4 xr = *(const float4*)(g1 + b);
    float4 hr = *(const float4*)(g2 + b);
    float4 xz = *(const float4*)(g1 + b + HH);
    float4 hz = *(const float4*)(g2 + b + HH);
    float4 xn = *(const float4*)(g1 + b + 2 * HH);
    float4 hn = *(const float4*)(g2 + b + 2 * HH);
    float4 hi4 = *(const float4*)(hin + (size_t)warp * HH + lane * 4);
    float4 o;
    {
        float r = 1.f / (1.f + __expf(-(xr.x + hr.x)));
        float z = 1.f / (1.f + __expf(-(xz.x + hz.x)));
        float n = tanhf(xn.x + r * hn.x);
        o.x = (1.f - z) * n + z * hi4.x;
    }
    {
        float r = 1.f / (1.f + __expf(-(xr.y + hr.y)));
        float z = 1.f / (1.f + __expf(-(xz.y + hz.y)));
        float n = tanhf(xn.y + r * hn.y);
        o.y = (1.f - z) * n + z * hi4.y;
    }
    {
        float r = 1.f / (1.f + __expf(-(xr.z + hr.z)));
        float z = 1.f / (1.f + __expf(-(xz.z + hz.z)));
        float n = tanhf(xn.z + r * hn.z);
        o.z = (1.f - z) * n + z * hi4.z;
    }
    {
        float r = 1.f / (1.f + __expf(-(xr.w + hr.w)));
        float z = 1.f / (1.f + __expf(-(xz.w + hz.w)));
        float n = tanhf(xn.w + r * hn.w);
        o.w = (1.f - z) * n + z * hi4.w;
    }
    *(float4*)(hout + (size_t)warp * HH + lane * 4) = o;
    #pragma unroll
    for (int a = 0; a < AA; ++a) {
        float4 w4 = *(const float4*)(Wt + a * HH + lane * 4);
        float p = o.x*w4.x + o.y*w4.y + o.z*w4.z + o.w*w4.w;
        #pragma unroll
        for (int off = 16; off > 0; off >>= 1) p += __shfl_xor_sync(0xffffffffu, p, off);
        if (lane == 0) qout[warp * AA + a] = p + bs[a];
    }
}

// ======================= launch =================================================
extern "C" void kernel_launch(void* const* d_in, const int* in_sizes, int n_in,
                              void* d_out, int out_size) {
    const float* x      = (const float*)d_in[0];
    const float* mask   = (const float*)d_in[1];
    const float* hidden = (const float*)d_in[2];
    const float* encW   = (const float*)d_in[3];
    const float* encb   = (const float*)d_in[4];
    const float* Wv1 = (const float*)d_in[5],  *bv1 = (const float*)d_in[6];
    const float* Wk1 = (const float*)d_in[7],  *bk1 = (const float*)d_in[8];
    const float* Wq1 = (const float*)d_in[9],  *bq1 = (const float*)d_in[10];
    const float* Wo1 = (const float*)d_in[11], *bo1 = (const float*)d_in[12];
    const float* Wv2 = (const float*)d_in[13], *bv2 = (const float*)d_in[14];
    const float* Wk2 = (const float*)d_in[15], *bk2 = (const float*)d_in[16];
    const float* Wq2 = (const float*)d_in[17], *bq2 = (const float*)d_in[18];
    const float* Wo2 = (const float*)d_in[19], *bo2 = (const float*)d_in[20];
    const float* Wih = (const float*)d_in[21], *bih = (const float*)d_in[22];
    const float* Whh = (const float*)d_in[23], *bhh = (const float*)d_in[24];
    const float* fcW = (const float*)d_in[25], *fcb = (const float*)d_in[26];

    float* out = (float*)d_out;
    float* qout = out;
    float* hout = out + (size_t)RB * AA;

    float *ph, *pt, *pg1, *pg2, *pbp1, *pbp2;
    uint4 *pBenc, *pBo1, *pBo2, *pBih, *pBhh, *pBv1, *pBv2;
    cudaGetSymbolAddress((void**)&ph,   g_h);
    cudaGetSymbolAddress((void**)&pt,   g_t);
    cudaGetSymbolAddress((void**)&pg1,  g_g1);
    cudaGetSymbolAddress((void**)&pg2,  g_g2);
    cudaGetSymbolAddress((void**)&pBenc, g_Benc);
    cudaGetSymbolAddress((void**)&pBo1,  g_Bo1);
    cudaGetSymbolAddress((void**)&pBo2,  g_Bo2);
    cudaGetSymbolAddress((void**)&pBih,  g_Bih);
    cudaGetSymbolAddress((void**)&pBhh,  g_Bhh);
    cudaGetSymbolAddress((void**)&pBv1,  g_Bv1);
    cudaGetSymbolAddress((void**)&pBv2,  g_Bv2);
    cudaGetSymbolAddress((void**)&pbp1,  g_bp1);
    cudaGetSymbolAddress((void**)&pbp2,  g_bp2);

    const int WB = 256;
    const int rowBlocks = RB / (WB / 32);     // 4000
    const int smemK128 = 64 * 64 * 4 * 2;     // 32 KB
    const int smemK64  = 64 * 32 * 4 * 2;     // 16 KB

    cudaFuncSetAttribute(mma_gemm_kernel<64,  true>,  cudaFuncAttributeMaxDynamicSharedMemorySize, smemK64);
    cudaFuncSetAttribute(mma_gemm_kernel<128, true>,  cudaFuncAttributeMaxDynamicSharedMemorySize, smemK128);
    cudaFuncSetAttribute(mma_gemm_dual_kernel<128, false>, cudaFuncAttributeMaxDynamicSharedMemorySize, smemK128);

    // ---- merged weight packing (single launch) + adjacency ----
    pack_all_kernel<<<(59648 + WB - 1) / WB, WB>>>(
        encW, Wo1, Wo2, Wih, Whh,
        Wv1, Wq1, Wk1, Wv2, Wq2, Wk2,
        bv1, bq1, bk1, bv2, bq2, bk2,
        pBenc, pBo1, pBo2, pBih, pBhh, pBv1, pBv2, pbp1, pbp2);
    build_adj_kernel<<<rowBlocks, WB>>>(mask);

    dim3 grid128(RB / 64, 1);    // (500,1)
    dim3 grid384(RB / 64, 3);    // (500,3)
    dim3 gridDual(2 * RB / 64, 3);  // (1000,3)

    // encoder: h1 = relu(x @ encW + encb)
    mma_gemm_kernel<64, true><<<grid128, WB, smemK64>>>(x, pBenc, encb, ph, HH);

    // ---- attention layer 1 ----
    mma_gemm_kernel<128, true><<<grid384, WB, smemK128>>>(ph, pBv1, pbp1, pg1, 3*HH);
    spattn_kernel<<<rowBlocks, WB>>>(pg1, pt);
    mma_gemm_kernel<128, true><<<grid128, WB, smemK128>>>(pt, pBo1, bo1, ph, HH);

    // ---- attention layer 2 ----
    mma_gemm_kernel<128, true><<<grid384, WB, smemK128>>>(ph, pBv2, pbp2, pg1, 3*HH);
    spattn_kernel<<<rowBlocks, WB>>>(pg1, pt);
    mma_gemm_kernel<128, true><<<grid128, WB, smemK128>>>(pt, pBo2, bo2, ph, HH);

    // ---- GRU GEMMs (merged into one launch) + fused gate/head ----
    mma_gemm_dual_kernel<128, false><<<gridDual, WB, smemK128>>>(
        ph, pBih, bih, pg1, hidden, pBhh, bhh, pg2, 3*HH, RB / 64);
    gru_fc_kernel<<<rowBlocks, WB>>>(pg1, pg2, hidden, fcW, fcb, hout, qout);

    (void)in_sizes; (void)n_in; (void)out_size;
}

// round 14
// speedup vs baseline: 1.2729x; 1.0356x over previous
#include <cuda_runtime.h>
#include <cuda_bf16.h>
#include <cstdint>

// Problem constants
#define BB   32
#define NN   1000
#define DIN  64
#define HH   128
#define AA   10
#define RB   (BB*NN)          // 32000 rows
#define MAXJ 128

// ======================= scratch (static device globals) ========================
__device__ float g_h  [RB*HH];
__device__ float g_t  [RB*HH];
__device__ float g_g1 [RB*3*HH];
__device__ float g_g2 [RB*3*HH];
__device__ int   g_adj[RB*MAXJ];
__device__ int   g_cnt[RB];
// fragment-packed weights: uint4 per (kstep, ntile, lane) = {bh0,bh1,bl0,bl1}
__device__ uint4 g_Benc[4*16*32];      // K=64,  N=128
__device__ uint4 g_Bo1 [8*16*32];      // K=128, N=128
__device__ uint4 g_Bo2 [8*16*32];
__device__ uint4 g_Bih [8*48*32];      // K=128, N=384
__device__ uint4 g_Bhh [8*48*32];
__device__ uint4 g_Bv1 [8*48*32];
__device__ uint4 g_Bv2 [8*48*32];
__device__ float g_bp1 [3*HH];
__device__ float g_bp2 [3*HH];

// ======================= helpers ================================================
__device__ __forceinline__ uint32_t smem_u32(const void* p) {
    uint32_t a;
    asm("{ .reg .u64 t; cvta.to.shared.u64 t, %1; cvt.u32.u64 %0, t; }" : "=r"(a) : "l"(p));
    return a;
}
__device__ __forceinline__ void bsplit(float v, uint16_t& h, uint16_t& l) {
    __nv_bfloat16 bh = __float2bfloat16(v);
    float fh = __bfloat162float(bh);
    __nv_bfloat16 bl = __float2bfloat16(v - fh);
    h = __bfloat16_as_ushort(bh);
    l = __bfloat16_as_ushort(bl);
}
__device__ __forceinline__ uint32_t pk(uint16_t lo, uint16_t hi) {
    return ((uint32_t)hi << 16) | lo;
}
// {trunc_bf16(a) in low half, trunc_bf16(b) in high half}
__device__ __forceinline__ uint32_t prmt_hi(uint32_t a, uint32_t b) {
    uint32_t r;
    asm("prmt.b32 %0, %1, %2, 0x7632;" : "=r"(r) : "r"(a), "r"(b));
    return r;
}
// {bf16(lo_val) in low half, bf16(hi_val) in high half}
__device__ __forceinline__ uint32_t cvt_bf16x2(float hi_val, float lo_val) {
    uint32_t r;
    asm("cvt.rn.bf16x2.f32 %0, %1, %2;" : "=r"(r) : "f"(hi_val), "f"(lo_val));
    return r;
}
#define MMA_BF16(d, a, b0, b1)                                                   \
    asm volatile("mma.sync.aligned.m16n8k16.row.col.f32.bf16.bf16.f32 "          \
                 "{%0,%1,%2,%3}, {%4,%5,%6,%7}, {%8,%9}, {%0,%1,%2,%3};"         \
                 : "+f"((d)[0]), "+f"((d)[1]), "+f"((d)[2]), "+f"((d)[3])        \
                 : "r"((a)[0]), "r"((a)[1]), "r"((a)[2]), "r"((a)[3]),           \
                   "r"(b0), "r"(b1))
#define LDSM_X4(r, addr)                                                         \
    asm volatile("ldmatrix.sync.aligned.m8n8.x4.shared.b16 {%0,%1,%2,%3}, [%4];" \
                 : "=r"((r)[0]), "=r"((r)[1]), "=r"((r)[2]), "=r"((r)[3])        \
                 : "r"(addr))

// ======================= merged weight packing ==================================
// b0 = {B[k0][n], B[k0+1][n]}, b1 = rows k0+8,k0+9; k0 = ks*16+(lane&3)*2,
// n = ntile*8 + (lane>>2).
__device__ __forceinline__ void pack_one(const float* __restrict__ W,
                                         uint4* __restrict__ Bp,
                                         int N, int K, int transb, int i) {
    int NT = N >> 3;
    int lane = i & 31, rest = i >> 5;
    int ntg = rest % NT, ks = rest / NT;
    int n = ntg * 8 + (lane >> 2);
    int k0 = ks * 16 + (lane & 3) * 2;
    float v[4];
    #pragma unroll
    for (int j = 0; j < 4; ++j) {
        int k = k0 + (j >> 1) * 8 + (j & 1);
        v[j] = transb ? W[n * K + k] : W[k * N + n];
    }
    uint16_t h[4], l[4];
    #pragma unroll
    for (int j = 0; j < 4; ++j) bsplit(v[j], h[j], l[j]);
    Bp[i] = make_uint4(pk(h[0], h[1]), pk(h[2], h[3]), pk(l[0], l[1]), pk(l[2], l[3]));
}
__device__ __forceinline__ void pack_one_vqk(const float* __restrict__ Wv,
                                             const float* __restrict__ Wq,
                                             const float* __restrict__ Wk,
                                             uint4* __restrict__ Bp, int i) {
    const int NT = 48, K = 128;
    int lane = i & 31, rest = i >> 5;
    int ntg = rest % NT, ks = rest / NT;
    int n = ntg * 8 + (lane >> 2);
    const float* W = (n < 128) ? Wv : (n < 256) ? Wq : Wk;
    int nn = n & 127;
    int k0 = ks * 16 + (lane & 3) * 2;
    float v[4];
    #pragma unroll
    for (int j = 0; j < 4; ++j) {
        int k = k0 + (j >> 1) * 8 + (j & 1);
        v[j] = W[k * K + nn];
    }
    uint16_t h[4], l[4];
    #pragma unroll
    for (int j = 0; j < 4; ++j) bsplit(v[j], h[j], l[j]);
    Bp[i] = make_uint4(pk(h[0], h[1]), pk(h[2], h[3]), pk(l[0], l[1]), pk(l[2], l[3]));
}

__global__ void pack_all_kernel(
    const float* encW, const float* Wo1, const float* Wo2,
    const float* Wih,  const float* Whh,
    const float* Wv1, const float* Wq1, const float* Wk1,
    const float* Wv2, const float* Wq2, const float* Wk2,
    const float* bv1, const float* bq1, const float* bk1,
    const float* bv2, const float* bq2, const float* bk2,
    uint4* Benc, uint4* Bo1, uint4* Bo2, uint4* Bih, uint4* Bhh,
    uint4* Bv1, uint4* Bv2, float* bp1, float* bp2) {
    int i = blockIdx.x * blockDim.x + threadIdx.x;
    if      (i < 2048)  pack_one(encW, Benc, 128, 64, 0, i);
    else if (i < 6144)  pack_one(Wo1, Bo1, 128, 128, 0, i - 2048);
    else if (i < 10240) pack_one(Wo2, Bo2, 128, 128, 0, i - 6144);
    else if (i < 22528) pack_one(Wih, Bih, 384, 128, 1, i - 10240);
    else if (i < 34816) pack_one(Whh, Bhh, 384, 128, 1, i - 22528);
    else if (i < 47104) pack_one_vqk(Wv1, Wq1, Wk1, Bv1, i - 34816);
    else if (i < 59392) pack_one_vqk(Wv2, Wq2, Wk2, Bv2, i - 47104);
    else if (i < 59520) { int j = i - 59392; bp1[j] = bv1[j]; bp1[128+j] = bq1[j]; bp1[256+j] = bk1[j]; }
    else if (i < 59648) { int j = i - 59520; bp2[j] = bv2[j]; bp2[128+j] = bq2[j]; bp2[256+j] = bk2[j]; }
}

// ======================= bf16x2 tensor-core GEMM core ===========================
// C[32000, NTOT] = relu?(A[32000,K] x B + bias).
// CTA tile 64x128, 4 warps (128 thr) = 2m x 2n, warp tile 32x64 (2mt x 8nt).
// ldmatrix A fragments; B fragment-packed in GMEM.
template<int K, bool RELU>
__device__ __forceinline__ void gemm_body(const float* __restrict__ A,
                                          const uint4* __restrict__ Bp,
                                          const float* __restrict__ bias,
                                          float* __restrict__ C,
                                          int NTOT, int bx, int by) {
    constexpr int KSTEPS = K / 16, KPAIRS = K / 2, F4R = K / 4;
    extern __shared__ uint32_t sA[];                  // Ah [64*KPAIRS] | Al [64*KPAIRS]
    uint32_t* Ah = sA;
    uint32_t* Al = sA + 64 * KPAIRS;
    const int tid = threadIdx.x, lane = tid & 31, wid = tid >> 5;
    const int mrow0 = bx * 64, ncol0 = by * 128;

    // ---- convert A tile fp32 -> hi(trunc)/lo bf16 pairs, XOR-swizzled ----
    #pragma unroll
    for (int c = 0; c < (64 * F4R) / 128; ++c) {
        int idx = tid + c * 128;
        int r = idx / F4R, q = idx % F4R;
        float4 v = *(const float4*)(A + (size_t)(mrow0 + r) * K + q * 4);
        uint32_t ax = __float_as_uint(v.x), ay = __float_as_uint(v.y);
        uint32_t az = __float_as_uint(v.z), aw = __float_as_uint(v.w);
        uint32_t h01 = prmt_hi(ax, ay);
        uint32_t h23 = prmt_hi(az, aw);
        float lx = v.x - __uint_as_float(ax & 0xFFFF0000u);
        float ly = v.y - __uint_as_float(ay & 0xFFFF0000u);
        float lz = v.z - __uint_as_float(az & 0xFFFF0000u);
        float lw = v.w - __uint_as_float(aw & 0xFFFF0000u);
        uint32_t l01 = cvt_bf16x2(ly, lx);    // low half = lx
        uint32_t l23 = cvt_bf16x2(lw, lz);
        int p0 = q * 2, sw = (r & 7) << 2, base = r * KPAIRS;
        Ah[base + (p0 ^ sw)]       = h01;
        Ah[base + ((p0 + 1) ^ sw)] = h23;
        Al[base + (p0 ^ sw)]       = l01;
        Al[base + ((p0 + 1) ^ sw)] = l23;
    }
    __syncthreads();

    const int wm = wid & 1, wn = wid >> 1;   // 2 m-warps x 2 n-warps
    const int g = lane >> 2, tg = lane & 3;
    const int NTtot = NTOT >> 3;
    const int ntbase = (ncol0 >> 3) + wn * 8;

    // ldmatrix lane mapping: lanes 0-7 -> rows 0-7 khalf0, 8-15 -> rows 8-15 khalf0,
    // 16-23 -> rows 0-7 khalf1, 24-31 -> rows 8-15 khalf1. Result m0..m3 = a0..a3.
    const int row_in = (lane & 7) | (((lane >> 3) & 1) << 3);
    const int c4 = ((lane >> 4) & 1) << 2;      // pair offset for k-half
    const int swl = (row_in & 7) << 2;          // mt adds 16 rows: (row&7) unchanged
    uint32_t abase[2], lbase[2];
    #pragma unroll
    for (int mt = 0; mt < 2; ++mt) {
        int row = wm * 32 + mt * 16 + row_in;
        abase[mt] = smem_u32(Ah + row * KPAIRS);
        lbase[mt] = smem_u32(Al + row * KPAIRS);
    }

    float acc[2][8][4];
    #pragma unroll
    for (int mt = 0; mt < 2; ++mt)
        #pragma unroll
        for (int nt = 0; nt < 8; ++nt)
            #pragma unroll
            for (int j = 0; j < 4; ++j) acc[mt][nt][j] = 0.f;

    #pragma unroll
    for (int ks = 0; ks < KSTEPS; ++ks) {
        uint32_t poff = (uint32_t)((((ks * 8) | c4) ^ swl) << 2);   // byte offset
        uint32_t ah[2][4], al[2][4];
        LDSM_X4(ah[0], abase[0] + poff);
        LDSM_X4(ah[1], abase[1] + poff);
        LDSM_X4(al[0], lbase[0] + poff);
        LDSM_X4(al[1], lbase[1] + poff);
        #pragma unroll
        for (int nt = 0; nt < 8; ++nt) {
            uint4 b = Bp[(size_t)(ks * NTtot + ntbase + nt) * 32 + lane];
            #pragma unroll
            for (int mt = 0; mt < 2; ++mt) {
                MMA_BF16(acc[mt][nt], ah[mt], b.x, b.y);   // hi*hi
                MMA_BF16(acc[mt][nt], al[mt], b.x, b.y);   // lo*hi
                MMA_BF16(acc[mt][nt], ah[mt], b.z, b.w);   // hi*lo
            }
        }
    }

    // ---- epilogue: bias (+relu) + store ----
    #pragma unroll
    for (int mt = 0; mt < 2; ++mt) {
        int row = mrow0 + wm * 32 + mt * 16 + g;
        #pragma unroll
        for (int nt = 0; nt < 8; ++nt) {
            int col = ncol0 + wn * 64 + nt * 8 + tg * 2;
            float b0 = bias[col], b1 = bias[col + 1];
            float2 v0 = make_float2(acc[mt][nt][0] + b0, acc[mt][nt][1] + b1);
            float2 v1 = make_float2(acc[mt][nt][2] + b0, acc[mt][nt][3] + b1);
            if (RELU) {
                v0.x = fmaxf(v0.x, 0.f); v0.y = fmaxf(v0.y, 0.f);
                v1.x = fmaxf(v1.x, 0.f); v1.y = fmaxf(v1.y, 0.f);
            }
            *(float2*)(C + (size_t)row * NTOT + col)       = v0;
            *(float2*)(C + (size_t)(row + 8) * NTOT + col) = v1;
        }
    }
}

template<int K, bool RELU>
__global__ __launch_bounds__(128, 4)
void mma_gemm_kernel(const float* __restrict__ A, const uint4* __restrict__ Bp,
                     const float* __restrict__ bias, float* __restrict__ C, int NTOT) {
    gemm_body<K, RELU>(A, Bp, bias, C, NTOT, blockIdx.x, blockIdx.y);
}

// Dual GEMM: two independent same-shape GEMMs in one launch (kills one tail).
template<int K, bool RELU>
__global__ __launch_bounds__(128, 4)
void mma_gemm_dual_kernel(const float* __restrict__ A0, const uint4* __restrict__ B0,
                          const float* __restrict__ c0, float* __restrict__ C0,
                          const float* __restrict__ A1, const uint4* __restrict__ B1,
                          const float* __restrict__ c1, float* __restrict__ C1,
                          int NTOT, int split) {
    int bx = blockIdx.x;
    if (bx < split) gemm_body<K, RELU>(A0, B0, c0, C0, NTOT, bx, blockIdx.y);
    else            gemm_body<K, RELU>(A1, B1, c1, C1, NTOT, bx - split, blockIdx.y);
}

// ======================= adjacency build ========================================
__global__ void build_adj_kernel(const float* __restrict__ mask) {
    int warp = (blockIdx.x * blockDim.x + threadIdx.x) >> 5;
    int lane = threadIdx.x & 31;
    if (warp >= RB) return;
    const float* row = mask + (size_t)warp * NN;
    int cnt = 0;
    for (int j0 = 0; j0 < NN; j0 += 32) {
        int j = j0 + lane;
        bool on = (j < NN) && (row[j] > 0.5f);
        unsigned bal = __ballot_sync(0xffffffffu, on);
        if (on) {
            int pos = cnt + __popc(bal & ((1u << lane) - 1u));
            if (pos < MAXJ) g_adj[warp * MAXJ + pos] = j;
        }
        cnt += __popc(bal);
    }
    if (lane == 0) g_cnt[warp] = min(cnt, MAXJ);
}

// ======================= sparse attention (warp/row, online softmax) ============
__global__ void spattn_kernel(const float* __restrict__ vqk, float* __restrict__ out) {
    int warp = (blockIdx.x * blockDim.x + threadIdx.x) >> 5;
    int lane = threadIdx.x & 31;
    if (warp >= RB) return;
    int base = (warp / NN) * NN;
    float4 q4 = *(const float4*)(vqk + (size_t)warp * 384 + 128 + lane * 4);
    int cnt = g_cnt[warp];
    const int* adj = g_adj + warp * MAXJ;
    float m = -3.4e38f, l = 0.f;
    float4 acc = make_float4(0.f, 0.f, 0.f, 0.f);
    for (int t = 0; t < cnt; ++t) {
        size_t j = (size_t)(base + adj[t]) * 384;
        float4 k4 = *(const float4*)(vqk + j + 256 + lane * 4);
        float p = q4.x*k4.x + q4.y*k4.y + q4.z*k4.z + q4.w*k4.w;
        #pragma unroll
        for (int o = 16; o > 0; o >>= 1) p += __shfl_xor_sync(0xffffffffu, p, o);
        float4 v4 = *(const float4*)(vqk + j + lane * 4);
        float nm = fmaxf(m, p);
        float sc = __expf(m - nm);
        float e  = __expf(p - nm);
        l = l * sc + e;
        acc.x = acc.x * sc + e * v4.x;
        acc.y = acc.y * sc + e * v4.y;
        acc.z = acc.z * sc + e * v4.z;
        acc.w = acc.w * sc + e * v4.w;
        m = nm;
    }
    float inv = 1.f / l;
    float4 o4 = make_float4(acc.x*inv, acc.y*inv, acc.z*inv, acc.w*inv);
    *(float4*)(out + (size_t)warp * HH + lane * 4) = o4;
}

// ======================= fused GRU gate + FC head (warp/row) ====================
__global__ void gru_fc_kernel(const float* __restrict__ g1, const float* __restrict__ g2,
                              const float* __restrict__ hin, const float* __restrict__ fcW,
                              const float* __restrict__ fcb,
                              float* __restrict__ hout, float* __restrict__ qout) {
    __shared__ float Wt[AA * HH];   // transposed: Wt[a*128 + k]
    __shared__ float bs[AA];
    int tid = threadIdx.x;
    for (int i = tid; i < AA * HH; i += blockDim.x) {
        int k = i / AA, a = i % AA;
        Wt[a * HH + k] = fcW[i];
    }
    if (tid < AA) bs[tid] = fcb[tid];
    __syncthreads();
    int warp = (blockIdx.x * blockDim.x + tid) >> 5;
    int lane = tid & 31;
    if (warp >= RB) return;
    size_t b = (size_t)warp * (3 * HH) + lane * 4;
    float4 xr = *(const float4*)(g1 + b);
    float4 hr = *(const float4*)(g2 + b);
    float4 xz = *(const float4*)(g1 + b + HH);
    float4 hz = *(const float4*)(g2 + b + HH);
    float4 xn = *(const float4*)(g1 + b + 2 * HH);
    float4 hn = *(const float4*)(g2 + b + 2 * HH);
    float4 hi4 = *(const float4*)(hin + (size_t)warp * HH + lane * 4);
    float4 o;
    {
        float r = 1.f / (1.f + __expf(-(xr.x + hr.x)));
        float z = 1.f / (1.f + __expf(-(xz.x + hz.x)));
        float n = tanhf(xn.x + r * hn.x);
        o.x = (1.f - z) * n + z * hi4.x;
    }
    {
        float r = 1.f / (1.f + __expf(-(xr.y + hr.y)));
        float z = 1.f / (1.f + __expf(-(xz.y + hz.y)));
        float n = tanhf(xn.y + r * hn.y);
        o.y = (1.f - z) * n + z * hi4.y;
    }
    {
        float r = 1.f / (1.f + __expf(-(xr.z + hr.z)));
        float z = 1.f / (1.f + __expf(-(xz.z + hz.z)));
        float n = tanhf(xn.z + r * hn.z);
        o.z = (1.f - z) * n + z * hi4.z;
    }
    {
        float r = 1.f / (1.f + __expf(-(xr.w + hr.w)));
        float z = 1.f / (1.f + __expf(-(xz.w + hz.w)));
        float n = tanhf(xn.w + r * hn.w);
        o.w = (1.f - z) * n + z * hi4.w;
    }
    *(float4*)(hout + (size_t)warp * HH + lane * 4) = o;
    #pragma unroll
    for (int a = 0; a < AA; ++a) {
        float4 w4 = *(const float4*)(Wt + a * HH + lane * 4);
        float p = o.x*w4.x + o.y*w4.y + o.z*w4.z + o.w*w4.w;
        #pragma unroll
        for (int off = 16; off > 0; off >>= 1) p += __shfl_xor_sync(0xffffffffu, p, off);
        if (lane == 0) qout[warp * AA + a] = p + bs[a];
    }
}

// ======================= launch =================================================
extern "C" void kernel_launch(void* const* d_in, const int* in_sizes, int n_in,
                              void* d_out, int out_size) {
    const float* x      = (const float*)d_in[0];
    const float* mask   = (const float*)d_in[1];
    const float* hidden = (const float*)d_in[2];
    const float* encW   = (const float*)d_in[3];
    const float* encb   = (const float*)d_in[4];
    const float* Wv1 = (const float*)d_in[5],  *bv1 = (const float*)d_in[6];
    const float* Wk1 = (const float*)d_in[7],  *bk1 = (const float*)d_in[8];
    const float* Wq1 = (const float*)d_in[9],  *bq1 = (const float*)d_in[10];
    const float* Wo1 = (const float*)d_in[11], *bo1 = (const float*)d_in[12];
    const float* Wv2 = (const float*)d_in[13], *bv2 = (const float*)d_in[14];
    const float* Wk2 = (const float*)d_in[15], *bk2 = (const float*)d_in[16];
    const float* Wq2 = (const float*)d_in[17], *bq2 = (const float*)d_in[18];
    const float* Wo2 = (const float*)d_in[19], *bo2 = (const float*)d_in[20];
    const float* Wih = (const float*)d_in[21], *bih = (const float*)d_in[22];
    const float* Whh = (const float*)d_in[23], *bhh = (const float*)d_in[24];
    const float* fcW = (const float*)d_in[25], *fcb = (const float*)d_in[26];

    float* out = (float*)d_out;
    float* qout = out;
    float* hout = out + (size_t)RB * AA;

    float *ph, *pt, *pg1, *pg2, *pbp1, *pbp2;
    uint4 *pBenc, *pBo1, *pBo2, *pBih, *pBhh, *pBv1, *pBv2;
    cudaGetSymbolAddress((void**)&ph,   g_h);
    cudaGetSymbolAddress((void**)&pt,   g_t);
    cudaGetSymbolAddress((void**)&pg1,  g_g1);
    cudaGetSymbolAddress((void**)&pg2,  g_g2);
    cudaGetSymbolAddress((void**)&pBenc, g_Benc);
    cudaGetSymbolAddress((void**)&pBo1,  g_Bo1);
    cudaGetSymbolAddress((void**)&pBo2,  g_Bo2);
    cudaGetSymbolAddress((void**)&pBih,  g_Bih);
    cudaGetSymbolAddress((void**)&pBhh,  g_Bhh);
    cudaGetSymbolAddress((void**)&pBv1,  g_Bv1);
    cudaGetSymbolAddress((void**)&pBv2,  g_Bv2);
    cudaGetSymbolAddress((void**)&pbp1,  g_bp1);
    cudaGetSymbolAddress((void**)&pbp2,  g_bp2);

    const int WB = 256;
    const int WG = 128;                       // GEMM block size (4 warps)
    const int rowBlocks = RB / (WB / 32);     // 4000
    const int smemK128 = 64 * 64 * 4 * 2;     // 32 KB
    const int smemK64  = 64 * 32 * 4 * 2;     // 16 KB

    cudaFuncSetAttribute(mma_gemm_kernel<64,  true>,  cudaFuncAttributeMaxDynamicSharedMemorySize, smemK64);
    cudaFuncSetAttribute(mma_gemm_kernel<128, true>,  cudaFuncAttributeMaxDynamicSharedMemorySize, smemK128);
    cudaFuncSetAttribute(mma_gemm_dual_kernel<128, false>, cudaFuncAttributeMaxDynamicSharedMemorySize, smemK128);

    // ---- merged weight packing (single launch) + adjacency ----
    pack_all_kernel<<<(59648 + WB - 1) / WB, WB>>>(
        encW, Wo1, Wo2, Wih, Whh,
        Wv1, Wq1, Wk1, Wv2, Wq2, Wk2,
        bv1, bq1, bk1, bv2, bq2, bk2,
        pBenc, pBo1, pBo2, pBih, pBhh, pBv1, pBv2, pbp1, pbp2);
    build_adj_kernel<<<rowBlocks, WB>>>(mask);

    dim3 grid128(RB / 64, 1);    // (500,1)
    dim3 grid384(RB / 64, 3);    // (500,3)
    dim3 gridDual(2 * RB / 64, 3);  // (1000,3)

    // encoder: h1 = relu(x @ encW + encb)
    mma_gemm_kernel<64, true><<<grid128, WG, smemK64>>>(x, pBenc, encb, ph, HH);

    // ---- attention layer 1 ----
    mma_gemm_kernel<128, true><<<grid384, WG, smemK128>>>(ph, pBv1, pbp1, pg1, 3*HH);
    spattn_kernel<<<rowBlocks, WB>>>(pg1, pt);
    mma_gemm_kernel<128, true><<<grid128, WG, smemK128>>>(pt, pBo1, bo1, ph, HH);

    // ---- attention layer 2 ----
    mma_gemm_kernel<128, true><<<grid384, WG, smemK128>>>(ph, pBv2, pbp2, pg1, 3*HH);
    spattn_kernel<<<rowBlocks, WB>>>(pg1, pt);
    mma_gemm_kernel<128, true><<<grid128, WG, smemK128>>>(pt, pBo2, bo2, ph, HH);

    // ---- GRU GEMMs (merged into one launch) + fused gate/head ----
    mma_gemm_dual_kernel<128, false><<<gridDual, WG, smemK128>>>(
        ph, pBih, bih, pg1, hidden, pBhh, bhh, pg2, 3*HH, RB / 64);
    gru_fc_kernel<<<rowBlocks, WB>>>(pg1, pg2, hidden, fcW, fcb, hout, qout);

    (void)in_sizes; (void)n_in; (void)out_size;
}

// round 15
// speedup vs baseline: 1.2820x; 1.0071x over previous
#include <cuda_runtime.h>
#include <cuda_fp16.h>
#include <cstdint>

// Problem constants
#define BB   32
#define NN   1000
#define DIN  64
#define HH   128
#define AA   10
#define RB   (BB*NN)          // 32000 rows
#define MAXJ 128

// ======================= scratch (static device globals) ========================
__device__ float g_h  [RB*HH];
__device__ float g_t  [RB*HH];
__device__ float g_g1 [RB*3*HH];
__device__ float g_g2 [RB*3*HH];
__device__ int   g_adj[RB*MAXJ];
__device__ int   g_cnt[RB];
// fragment-packed fp16 weights: uint2 per (kstep, ntile, lane) = {bh0,bh1}
__device__ uint2 g_Benc[4*16*32];      // K=64,  N=128
__device__ uint2 g_Bo1 [8*16*32];      // K=128, N=128
__device__ uint2 g_Bo2 [8*16*32];
__device__ uint2 g_Bih [8*48*32];      // K=128, N=384
__device__ uint2 g_Bhh [8*48*32];
__device__ uint2 g_Bv1 [8*48*32];
__device__ uint2 g_Bv2 [8*48*32];
__device__ float g_bp1 [3*HH];
__device__ float g_bp2 [3*HH];

// ======================= helpers ================================================
__device__ __forceinline__ uint32_t smem_u32(const void* p) {
    uint32_t a;
    asm("{ .reg .u64 t; cvta.to.shared.u64 t, %1; cvt.u32.u64 %0, t; }" : "=r"(a) : "l"(p));
    return a;
}
__device__ __forceinline__ uint32_t pk(uint16_t lo, uint16_t hi) {
    return ((uint32_t)hi << 16) | lo;
}
#define MMA_F16(d, a, b0, b1)                                                    \
    asm volatile("mma.sync.aligned.m16n8k16.row.col.f32.f16.f16.f32 "            \
                 "{%0,%1,%2,%3}, {%4,%5,%6,%7}, {%8,%9}, {%0,%1,%2,%3};"         \
                 : "+f"((d)[0]), "+f"((d)[1]), "+f"((d)[2]), "+f"((d)[3])        \
                 : "r"((a)[0]), "r"((a)[1]), "r"((a)[2]), "r"((a)[3]),           \
                   "r"(b0), "r"(b1))
#define LDSM_X4(r, addr)                                                         \
    asm volatile("ldmatrix.sync.aligned.m8n8.x4.shared.b16 {%0,%1,%2,%3}, [%4];" \
                 : "=r"((r)[0]), "=r"((r)[1]), "=r"((r)[2]), "=r"((r)[3])        \
                 : "r"(addr))

// ======================= merged weight packing (fp16 rn) ========================
// b0 = {B[k0][n], B[k0+1][n]}, b1 = rows k0+8,k0+9; k0 = ks*16+(lane&3)*2,
// n = ntile*8 + (lane>>2).
__device__ __forceinline__ void pack_one(const float* __restrict__ W,
                                         uint2* __restrict__ Bp,
                                         int N, int K, int transb, int i) {
    int NT = N >> 3;
    int lane = i & 31, rest = i >> 5;
    int ntg = rest % NT, ks = rest / NT;
    int n = ntg * 8 + (lane >> 2);
    int k0 = ks * 16 + (lane & 3) * 2;
    uint16_t h[4];
    #pragma unroll
    for (int j = 0; j < 4; ++j) {
        int k = k0 + (j >> 1) * 8 + (j & 1);
        float v = transb ? W[n * K + k] : W[k * N + n];
        h[j] = __half_as_ushort(__float2half_rn(v));
    }
    Bp[i] = make_uint2(pk(h[0], h[1]), pk(h[2], h[3]));
}
__device__ __forceinline__ void pack_one_vqk(const float* __restrict__ Wv,
                                             const float* __restrict__ Wq,
                                             const float* __restrict__ Wk,
                                             uint2* __restrict__ Bp, int i) {
    const int NT = 48, K = 128;
    int lane = i & 31, rest = i >> 5;
    int ntg = rest % NT, ks = rest / NT;
    int n = ntg * 8 + (lane >> 2);
    const float* W = (n < 128) ? Wv : (n < 256) ? Wq : Wk;
    int nn = n & 127;
    int k0 = ks * 16 + (lane & 3) * 2;
    uint16_t h[4];
    #pragma unroll
    for (int j = 0; j < 4; ++j) {
        int k = k0 + (j >> 1) * 8 + (j & 1);
        h[j] = __half_as_ushort(__float2half_rn(W[k * K + nn]));
    }
    Bp[i] = make_uint2(pk(h[0], h[1]), pk(h[2], h[3]));
}

__global__ void pack_all_kernel(
    const float* encW, const float* Wo1, const float* Wo2,
    const float* Wih,  const float* Whh,
    const float* Wv1, const float* Wq1, const float* Wk1,
    const float* Wv2, const float* Wq2, const float* Wk2,
    const float* bv1, const float* bq1, const float* bk1,
    const float* bv2, const float* bq2, const float* bk2,
    uint2* Benc, uint2* Bo1, uint2* Bo2, uint2* Bih, uint2* Bhh,
    uint2* Bv1, uint2* Bv2, float* bp1, float* bp2) {
    int i = blockIdx.x * blockDim.x + threadIdx.x;
    if      (i < 2048)  pack_one(encW, Benc, 128, 64, 0, i);
    else if (i < 6144)  pack_one(Wo1, Bo1, 128, 128, 0, i - 2048);
    else if (i < 10240) pack_one(Wo2, Bo2, 128, 128, 0, i - 6144);
    else if (i < 22528) pack_one(Wih, Bih, 384, 128, 1, i - 10240);
    else if (i < 34816) pack_one(Whh, Bhh, 384, 128, 1, i - 22528);
    else if (i < 47104) pack_one_vqk(Wv1, Wq1, Wk1, Bv1, i - 34816);
    else if (i < 59392) pack_one_vqk(Wv2, Wq2, Wk2, Bv2, i - 47104);
    else if (i < 59520) { int j = i - 59392; bp1[j] = bv1[j]; bp1[128+j] = bq1[j]; bp1[256+j] = bk1[j]; }
    else if (i < 59648) { int j = i - 59520; bp2[j] = bv2[j]; bp2[128+j] = bq2[j]; bp2[256+j] = bk2[j]; }
}

// ======================= fp16 2-term tensor-core GEMM ===========================
// C[32000, NTOT] = relu?(A[32000,K] x B + bias), B = f16_rn(W).
// A = Ah + Al (fp16 rn split); D = Ah*B + Al*B  (dropped residual ~2^-12 of B).
// CTA tile 64x128, 4 warps (128 thr) = 2m x 2n, warp tile 32x64 (2mt x 8nt).
template<int K, bool RELU>
__device__ __forceinline__ void gemm_body(const float* __restrict__ A,
                                          const uint2* __restrict__ Bp,
                                          const float* __restrict__ bias,
                                          float* __restrict__ C,
                                          int NTOT, int bx, int by) {
    constexpr int KSTEPS = K / 16, KPAIRS = K / 2, F4R = K / 4;
    extern __shared__ uint32_t sA[];                  // Ah [64*KPAIRS] | Al [64*KPAIRS]
    uint32_t* Ah = sA;
    uint32_t* Al = sA + 64 * KPAIRS;
    const int tid = threadIdx.x, lane = tid & 31, wid = tid >> 5;
    const int mrow0 = bx * 64, ncol0 = by * 128;

    // ---- convert A tile fp32 -> hi/lo fp16 (rn) pairs, XOR-swizzled ----
    #pragma unroll
    for (int c = 0; c < (64 * F4R) / 128; ++c) {
        int idx = tid + c * 128;
        int r = idx / F4R, q = idx % F4R;
        float4 v = *(const float4*)(A + (size_t)(mrow0 + r) * K + q * 4);
        __half hx = __float2half_rn(v.x), hy = __float2half_rn(v.y);
        __half hz = __float2half_rn(v.z), hw = __float2half_rn(v.w);
        __half lx = __float2half_rn(v.x - __half2float(hx));
        __half ly = __float2half_rn(v.y - __half2float(hy));
        __half lz = __float2half_rn(v.z - __half2float(hz));
        __half lw = __float2half_rn(v.w - __half2float(hw));
        uint32_t h01 = pk(__half_as_ushort(hx), __half_as_ushort(hy));
        uint32_t h23 = pk(__half_as_ushort(hz), __half_as_ushort(hw));
        uint32_t l01 = pk(__half_as_ushort(lx), __half_as_ushort(ly));
        uint32_t l23 = pk(__half_as_ushort(lz), __half_as_ushort(lw));
        int p0 = q * 2, sw = (r & 7) << 2, base = r * KPAIRS;
        Ah[base + (p0 ^ sw)]       = h01;
        Ah[base + ((p0 + 1) ^ sw)] = h23;
        Al[base + (p0 ^ sw)]       = l01;
        Al[base + ((p0 + 1) ^ sw)] = l23;
    }
    __syncthreads();

    const int wm = wid & 1, wn = wid >> 1;   // 2 m-warps x 2 n-warps
    const int g = lane >> 2, tg = lane & 3;
    const int NTtot = NTOT >> 3;
    const int ntbase = (ncol0 >> 3) + wn * 8;

    // ldmatrix lane mapping: lanes 0-7 -> rows 0-7 khalf0, 8-15 -> rows 8-15 khalf0,
    // 16-23 -> rows 0-7 khalf1, 24-31 -> rows 8-15 khalf1. Result m0..m3 = a0..a3.
    const int row_in = (lane & 7) | (((lane >> 3) & 1) << 3);
    const int c4 = ((lane >> 4) & 1) << 2;      // pair offset for k-half
    const int swl = (row_in & 7) << 2;          // mt adds 16 rows: (row&7) unchanged
    uint32_t abase[2], lbase[2];
    #pragma unroll
    for (int mt = 0; mt < 2; ++mt) {
        int row = wm * 32 + mt * 16 + row_in;
        abase[mt] = smem_u32(Ah + row * KPAIRS);
        lbase[mt] = smem_u32(Al + row * KPAIRS);
    }

    float acc[2][8][4];
    #pragma unroll
    for (int mt = 0; mt < 2; ++mt)
        #pragma unroll
        for (int nt = 0; nt < 8; ++nt)
            #pragma unroll
            for (int j = 0; j < 4; ++j) acc[mt][nt][j] = 0.f;

    #pragma unroll
    for (int ks = 0; ks < KSTEPS; ++ks) {
        uint32_t poff = (uint32_t)((((ks * 8) | c4) ^ swl) << 2);   // byte offset
        uint32_t ah[2][4], al[2][4];
        LDSM_X4(ah[0], abase[0] + poff);
        LDSM_X4(ah[1], abase[1] + poff);
        LDSM_X4(al[0], lbase[0] + poff);
        LDSM_X4(al[1], lbase[1] + poff);
        #pragma unroll
        for (int nt = 0; nt < 8; ++nt) {
            uint2 b = Bp[(size_t)(ks * NTtot + ntbase + nt) * 32 + lane];
            #pragma unroll
            for (int mt = 0; mt < 2; ++mt) {
                MMA_F16(acc[mt][nt], ah[mt], b.x, b.y);   // hi*B
                MMA_F16(acc[mt][nt], al[mt], b.x, b.y);   // lo*B
            }
        }
    }

    // ---- epilogue: bias (+relu) + store ----
    #pragma unroll
    for (int mt = 0; mt < 2; ++mt) {
        int row = mrow0 + wm * 32 + mt * 16 + g;
        #pragma unroll
        for (int nt = 0; nt < 8; ++nt) {
            int col = ncol0 + wn * 64 + nt * 8 + tg * 2;
            float b0 = bias[col], b1 = bias[col + 1];
            float2 v0 = make_float2(acc[mt][nt][0] + b0, acc[mt][nt][1] + b1);
            float2 v1 = make_float2(acc[mt][nt][2] + b0, acc[mt][nt][3] + b1);
            if (RELU) {
                v0.x = fmaxf(v0.x, 0.f); v0.y = fmaxf(v0.y, 0.f);
                v1.x = fmaxf(v1.x, 0.f); v1.y = fmaxf(v1.y, 0.f);
            }
            *(float2*)(C + (size_t)row * NTOT + col)       = v0;
            *(float2*)(C + (size_t)(row + 8) * NTOT + col) = v1;
        }
    }
}

template<int K, bool RELU>
__global__ __launch_bounds__(128, 4)
void mma_gemm_kernel(const float* __restrict__ A, const uint2* __restrict__ Bp,
                     const float* __restrict__ bias, float* __restrict__ C, int NTOT) {
    gemm_body<K, RELU>(A, Bp, bias, C, NTOT, blockIdx.x, blockIdx.y);
}

// Dual GEMM: two independent same-shape GEMMs in one launch (kills one tail).
template<int K, bool RELU>
__global__ __launch_bounds__(128, 4)
void mma_gemm_dual_kernel(const float* __restrict__ A0, const uint2* __restrict__ B0,
                          const float* __restrict__ c0, float* __restrict__ C0,
                          const float* __restrict__ A1, const uint2* __restrict__ B1,
                          const float* __restrict__ c1, float* __restrict__ C1,
                          int NTOT, int split) {
    int bx = blockIdx.x;
    if (bx < split) gemm_body<K, RELU>(A0, B0, c0, C0, NTOT, bx, blockIdx.y);
    else            gemm_body<K, RELU>(A1, B1, c1, C1, NTOT, bx - split, blockIdx.y);
}

// ======================= adjacency build ========================================
__global__ void build_adj_kernel(const float* __restrict__ mask) {
    int warp = (blockIdx.x * blockDim.x + threadIdx.x) >> 5;
    int lane = threadIdx.x & 31;
    if (warp >= RB) return;
    const float* row = mask + (size_t)warp * NN;
    int cnt = 0;
    for (int j0 = 0; j0 < NN; j0 += 32) {
        int j = j0 + lane;
        bool on = (j < NN) && (row[j] > 0.5f);
        unsigned bal = __ballot_sync(0xffffffffu, on);
        if (on) {
            int pos = cnt + __popc(bal & ((1u << lane) - 1u));
            if (pos < MAXJ) g_adj[warp * MAXJ + pos] = j;
        }
        cnt += __popc(bal);
    }
    if (lane == 0) g_cnt[warp] = min(cnt, MAXJ);
}

// ======================= sparse attention (warp/row, online softmax) ============
__global__ void spattn_kernel(const float* __restrict__ vqk, float* __restrict__ out) {
    int warp = (blockIdx.x * blockDim.x + threadIdx.x) >> 5;
    int lane = threadIdx.x & 31;
    if (warp >= RB) return;
    int base = (warp / NN) * NN;
    float4 q4 = *(const float4*)(vqk + (size_t)warp * 384 + 128 + lane * 4);
    int cnt = g_cnt[warp];
    const int* adj = g_adj + warp * MAXJ;
    float m = -3.4e38f, l = 0.f;
    float4 acc = make_float4(0.f, 0.f, 0.f, 0.f);
    for (int t = 0; t < cnt; ++t) {
        size_t j = (size_t)(base + adj[t]) * 384;
        float4 k4 = *(const float4*)(vqk + j + 256 + lane * 4);
        float p = q4.x*k4.x + q4.y*k4.y + q4.z*k4.z + q4.w*k4.w;
        #pragma unroll
        for (int o = 16; o > 0; o >>= 1) p += __shfl_xor_sync(0xffffffffu, p, o);
        float4 v4 = *(const float4*)(vqk + j + lane * 4);
        float nm = fmaxf(m, p);
        float sc = __expf(m - nm);
        float e  = __expf(p - nm);
        l = l * sc + e;
        acc.x = acc.x * sc + e * v4.x;
        acc.y = acc.y * sc + e * v4.y;
        acc.z = acc.z * sc + e * v4.z;
        acc.w = acc.w * sc + e * v4.w;
        m = nm;
    }
    float inv = 1.f / l;
    float4 o4 = make_float4(acc.x*inv, acc.y*inv, acc.z*inv, acc.w*inv);
    *(float4*)(out + (size_t)warp * HH + lane * 4) = o4;
}

// ======================= fused GRU gate + FC head (warp/row) ====================
__global__ void gru_fc_kernel(const float* __restrict__ g1, const float* __restrict__ g2,
                              const float* __restrict__ hin, const float* __restrict__ fcW,
                              const float* __restrict__ fcb,
                              float* __restrict__ hout, float* __restrict__ qout) {
    __shared__ float Wt[AA * HH];   // transposed: Wt[a*128 + k]
    __shared__ float bs[AA];
    int tid = threadIdx.x;
    for (int i = tid; i < AA * HH; i += blockDim.x) {
        int k = i / AA, a = i % AA;
        Wt[a * HH + k] = fcW[i];
    }
    if (tid < AA) bs[tid] = fcb[tid];
    __syncthreads();
    int warp = (blockIdx.x * blockDim.x + tid) >> 5;
    int lane = tid & 31;
    if (warp >= RB) return;
    size_t b = (size_t)warp * (3 * HH) + lane * 4;
    float4 xr = *(const float4*)(g1 + b);
    float4 hr = *(const float4*)(g2 + b);
    float4 xz = *(const float4*)(g1 + b + HH);
    float4 hz = *(const float4*)(g2 + b + HH);
    float4 xn = *(const float4*)(g1 + b + 2 * HH);
    float4 hn = *(const float4*)(g2 + b + 2 * HH);
    float4 hi4 = *(const float4*)(hin + (size_t)warp * HH + lane * 4);
    float4 o;
    {
        float r = 1.f / (1.f + __expf(-(xr.x + hr.x)));
        float z = 1.f / (1.f + __expf(-(xz.x + hz.x)));
        float n = tanhf(xn.x + r * hn.x);
        o.x = (1.f - z) * n + z * hi4.x;
    }
    {
        float r = 1.f / (1.f + __expf(-(xr.y + hr.y)));
        float z = 1.f / (1.f + __expf(-(xz.y + hz.y)));
        float n = tanhf(xn.y + r * hn.y);
        o.y = (1.f - z) * n + z * hi4.y;
    }
    {
        float r = 1.f / (1.f + __expf(-(xr.z + hr.z)));
        float z = 1.f / (1.f + __expf(-(xz.z + hz.z)));
        float n = tanhf(xn.z + r * hn.z);
        o.z = (1.f - z) * n + z * hi4.z;
    }
    {
        float r = 1.f / (1.f + __expf(-(xr.w + hr.w)));
        float z = 1.f / (1.f + __expf(-(xz.w + hz.w)));
        float n = tanhf(xn.w + r * hn.w);
        o.w = (1.f - z) * n + z * hi4.w;
    }
    *(float4*)(hout + (size_t)warp * HH + lane * 4) = o;
    #pragma unroll
    for (int a = 0; a < AA; ++a) {
        float4 w4 = *(const float4*)(Wt + a * HH + lane * 4);
        float p = o.x*w4.x + o.y*w4.y + o.z*w4.z + o.w*w4.w;
        #pragma unroll
        for (int off = 16; off > 0; off >>= 1) p += __shfl_xor_sync(0xffffffffu, p, off);
        if (lane == 0) qout[warp * AA + a] = p + bs[a];
    }
}

// ======================= launch =================================================
extern "C" void kernel_launch(void* const* d_in, const int* in_sizes, int n_in,
                              void* d_out, int out_size) {
    const float* x      = (const float*)d_in[0];
    const float* mask   = (const float*)d_in[1];
    const float* hidden = (const float*)d_in[2];
    const float* encW   = (const float*)d_in[3];
    const float* encb   = (const float*)d_in[4];
    const float* Wv1 = (const float*)d_in[5],  *bv1 = (const float*)d_in[6];
    const float* Wk1 = (const float*)d_in[7],  *bk1 = (const float*)d_in[8];
    const float* Wq1 = (const float*)d_in[9],  *bq1 = (const float*)d_in[10];
    const float* Wo1 = (const float*)d_in[11], *bo1 = (const float*)d_in[12];
    const float* Wv2 = (const float*)d_in[13], *bv2 = (const float*)d_in[14];
    const float* Wk2 = (const float*)d_in[15], *bk2 = (const float*)d_in[16];
    const float* Wq2 = (const float*)d_in[17], *bq2 = (const float*)d_in[18];
    const float* Wo2 = (const float*)d_in[19], *bo2 = (const float*)d_in[20];
    const float* Wih = (const float*)d_in[21], *bih = (const float*)d_in[22];
    const float* Whh = (const float*)d_in[23], *bhh = (const float*)d_in[24];
    const float* fcW = (const float*)d_in[25], *fcb = (const float*)d_in[26];

    float* out = (float*)d_out;
    float* qout = out;
    float* hout = out + (size_t)RB * AA;

    float *ph, *pt, *pg1, *pg2, *pbp1, *pbp2;
    uint2 *pBenc, *pBo1, *pBo2, *pBih, *pBhh, *pBv1, *pBv2;
    cudaGetSymbolAddress((void**)&ph,   g_h);
    cudaGetSymbolAddress((void**)&pt,   g_t);
    cudaGetSymbolAddress((void**)&pg1,  g_g1);
    cudaGetSymbolAddress((void**)&pg2,  g_g2);
    cudaGetSymbolAddress((void**)&pBenc, g_Benc);
    cudaGetSymbolAddress((void**)&pBo1,  g_Bo1);
    cudaGetSymbolAddress((void**)&pBo2,  g_Bo2);
    cudaGetSymbolAddress((void**)&pBih,  g_Bih);
    cudaGetSymbolAddress((void**)&pBhh,  g_Bhh);
    cudaGetSymbolAddress((void**)&pBv1,  g_Bv1);
    cudaGetSymbolAddress((void**)&pBv2,  g_Bv2);
    cudaGetSymbolAddress((void**)&pbp1,  g_bp1);
    cudaGetSymbolAddress((void**)&pbp2,  g_bp2);

    const int WB = 256;
    const int WG = 128;                       // GEMM block size (4 warps)
    const int rowBlocks = RB / (WB / 32);     // 4000
    const int smemK128 = 64 * 64 * 4 * 2;     // 32 KB
    const int smemK64  = 64 * 32 * 4 * 2;     // 16 KB

    cudaFuncSetAttribute(mma_gemm_kernel<64,  true>,  cudaFuncAttributeMaxDynamicSharedMemorySize, smemK64);
    cudaFuncSetAttribute(mma_gemm_kernel<128, true>,  cudaFuncAttributeMaxDynamicSharedMemorySize, smemK128);
    cudaFuncSetAttribute(mma_gemm_dual_kernel<128, false>, cudaFuncAttributeMaxDynamicSharedMemorySize, smemK128);

    // ---- merged weight packing (single launch) + adjacency ----
    pack_all_kernel<<<(59648 + WB - 1) / WB, WB>>>(
        encW, Wo1, Wo2, Wih, Whh,
        Wv1, Wq1, Wk1, Wv2, Wq2, Wk2,
        bv1, bq1, bk1, bv2, bq2, bk2,
        pBenc, pBo1, pBo2, pBih, pBhh, pBv1, pBv2, pbp1, pbp2);
    build_adj_kernel<<<rowBlocks, WB>>>(mask);

    dim3 grid128(RB / 64, 1);    // (500,1)
    dim3 grid384(RB / 64, 3);    // (500,3)
    dim3 gridDual(2 * RB / 64, 3);  // (1000,3)

    // encoder: h1 = relu(x @ encW + encb)
    mma_gemm_kernel<64, true><<<grid128, WG, smemK64>>>(x, pBenc, encb, ph, HH);

    // ---- attention layer 1 ----
    mma_gemm_kernel<128, true><<<grid384, WG, smemK128>>>(ph, pBv1, pbp1, pg1, 3*HH);
    spattn_kernel<<<rowBlocks, WB>>>(pg1, pt);
    mma_gemm_kernel<128, true><<<grid128, WG, smemK128>>>(pt, pBo1, bo1, ph, HH);

    // ---- attention layer 2 ----
    mma_gemm_kernel<128, true><<<grid384, WG, smemK128>>>(ph, pBv2, pbp2, pg1, 3*HH);
    spattn_kernel<<<rowBlocks, WB>>>(pg1, pt);
    mma_gemm_kernel<128, true><<<grid128, WG, smemK128>>>(pt, pBo2, bo2, ph, HH);

    // ---- GRU GEMMs (merged into one launch) + fused gate/head ----
    mma_gemm_dual_kernel<128, false><<<gridDual, WG, smemK128>>>(
        ph, pBih, bih, pg1, hidden, pBhh, bhh, pg2, 3*HH, RB / 64);
    gru_fc_kernel<<<rowBlocks, WB>>>(pg1, pg2, hidden, fcW, fcb, hout, qout);

    (void)in_sizes; (void)n_in; (void)out_size;
}

// round 16
// speedup vs baseline: 1.3769x; 1.0741x over previous
#include <cuda_runtime.h>
#include <cuda_fp16.h>
#include <cstdint>

// Problem constants
#define BB   32
#define NN   1000
#define DIN  64
#define HH   128
#define AA   10
#define RB   (BB*NN)          // 32000 rows
#define MAXJ 128

// ======================= scratch (static device globals) ========================
__device__ float g_h  [RB*HH];
__device__ float g_t  [RB*HH];
__device__ float g_g1 [RB*3*HH];
__device__ float g_g2 [RB*3*HH];
__device__ int   g_adj[RB*MAXJ];
__device__ int   g_cnt[RB];
// fragment-packed fp16 weights: uint2 per (kstep, ntile, lane) = {bh0,bh1}
__device__ uint2 g_Benc[4*16*32];      // K=64,  N=128
__device__ uint2 g_Bo1 [8*16*32];      // K=128, N=128
__device__ uint2 g_Bo2 [8*16*32];
__device__ uint2 g_Bih [8*48*32];      // K=128, N=384
__device__ uint2 g_Bhh [8*48*32];
__device__ uint2 g_Bv1 [8*48*32];
__device__ uint2 g_Bv2 [8*48*32];
__device__ float g_bp1 [3*HH];
__device__ float g_bp2 [3*HH];

// ======================= helpers ================================================
__device__ __forceinline__ uint32_t smem_u32(const void* p) {
    uint32_t a;
    asm("{ .reg .u64 t; cvta.to.shared.u64 t, %1; cvt.u32.u64 %0, t; }" : "=r"(a) : "l"(p));
    return a;
}
__device__ __forceinline__ uint32_t pk(uint16_t lo, uint16_t hi) {
    return ((uint32_t)hi << 16) | lo;
}
#define MMA_F16(d, a, b0, b1)                                                    \
    asm volatile("mma.sync.aligned.m16n8k16.row.col.f32.f16.f16.f32 "            \
                 "{%0,%1,%2,%3}, {%4,%5,%6,%7}, {%8,%9}, {%0,%1,%2,%3};"         \
                 : "+f"((d)[0]), "+f"((d)[1]), "+f"((d)[2]), "+f"((d)[3])        \
                 : "r"((a)[0]), "r"((a)[1]), "r"((a)[2]), "r"((a)[3]),           \
                   "r"(b0), "r"(b1))
#define LDSM_X4(r, addr)                                                         \
    asm volatile("ldmatrix.sync.aligned.m8n8.x4.shared.b16 {%0,%1,%2,%3}, [%4];" \
                 : "=r"((r)[0]), "=r"((r)[1]), "=r"((r)[2]), "=r"((r)[3])        \
                 : "r"(addr))

// ======================= merged weight packing (fp16 rn) ========================
// b0 = {B[k0][n], B[k0+1][n]}, b1 = rows k0+8,k0+9; k0 = ks*16+(lane&3)*2,
// n = ntile*8 + (lane>>2).
__device__ __forceinline__ void pack_one(const float* __restrict__ W,
                                         uint2* __restrict__ Bp,
                                         int N, int K, int transb, int i) {
    int NT = N >> 3;
    int lane = i & 31, rest = i >> 5;
    int ntg = rest % NT, ks = rest / NT;
    int n = ntg * 8 + (lane >> 2);
    int k0 = ks * 16 + (lane & 3) * 2;
    uint16_t h[4];
    #pragma unroll
    for (int j = 0; j < 4; ++j) {
        int k = k0 + (j >> 1) * 8 + (j & 1);
        float v = transb ? W[n * K + k] : W[k * N + n];
        h[j] = __half_as_ushort(__float2half_rn(v));
    }
    Bp[i] = make_uint2(pk(h[0], h[1]), pk(h[2], h[3]));
}
__device__ __forceinline__ void pack_one_vqk(const float* __restrict__ Wv,
                                             const float* __restrict__ Wq,
                                             const float* __restrict__ Wk,
                                             uint2* __restrict__ Bp, int i) {
    const int NT = 48, K = 128;
    int lane = i & 31, rest = i >> 5;
    int ntg = rest % NT, ks = rest / NT;
    int n = ntg * 8 + (lane >> 2);
    const float* W = (n < 128) ? Wv : (n < 256) ? Wq : Wk;
    int nn = n & 127;
    int k0 = ks * 16 + (lane & 3) * 2;
    uint16_t h[4];
    #pragma unroll
    for (int j = 0; j < 4; ++j) {
        int k = k0 + (j >> 1) * 8 + (j & 1);
        h[j] = __half_as_ushort(__float2half_rn(W[k * K + nn]));
    }
    Bp[i] = make_uint2(pk(h[0], h[1]), pk(h[2], h[3]));
}

__global__ void pack_all_kernel(
    const float* encW, const float* Wo1, const float* Wo2,
    const float* Wih,  const float* Whh,
    const float* Wv1, const float* Wq1, const float* Wk1,
    const float* Wv2, const float* Wq2, const float* Wk2,
    const float* bv1, const float* bq1, const float* bk1,
    const float* bv2, const float* bq2, const float* bk2,
    uint2* Benc, uint2* Bo1, uint2* Bo2, uint2* Bih, uint2* Bhh,
    uint2* Bv1, uint2* Bv2, float* bp1, float* bp2) {
    int i = blockIdx.x * blockDim.x + threadIdx.x;
    if      (i < 2048)  pack_one(encW, Benc, 128, 64, 0, i);
    else if (i < 6144)  pack_one(Wo1, Bo1, 128, 128, 0, i - 2048);
    else if (i < 10240) pack_one(Wo2, Bo2, 128, 128, 0, i - 6144);
    else if (i < 22528) pack_one(Wih, Bih, 384, 128, 1, i - 10240);
    else if (i < 34816) pack_one(Whh, Bhh, 384, 128, 1, i - 22528);
    else if (i < 47104) pack_one_vqk(Wv1, Wq1, Wk1, Bv1, i - 34816);
    else if (i < 59392) pack_one_vqk(Wv2, Wq2, Wk2, Bv2, i - 47104);
    else if (i < 59520) { int j = i - 59392; bp1[j] = bv1[j]; bp1[128+j] = bq1[j]; bp1[256+j] = bk1[j]; }
    else if (i < 59648) { int j = i - 59520; bp2[j] = bv2[j]; bp2[128+j] = bq2[j]; bp2[256+j] = bk2[j]; }
}

// ======================= fp16 2-term tensor-core GEMM ===========================
// C[32000, NTOT] = relu?(A[32000,K] x B + bias), B = f16_rn(W).
// A = Ah + Al (fp16 rn split); D = Ah*B + Al*B  (dropped residual ~2^-12 of B).
// CTA tile 64x128, 4 warps (128 thr) = 2m x 2n, warp tile 32x64 (2mt x 8nt).
template<int K, bool RELU>
__device__ __forceinline__ void gemm_body(const float* __restrict__ A,
                                          const uint2* __restrict__ Bp,
                                          const float* __restrict__ bias,
                                          float* __restrict__ C,
                                          int NTOT, int bx, int by) {
    constexpr int KSTEPS = K / 16, KPAIRS = K / 2, F4R = K / 4;
    extern __shared__ uint32_t sA[];                  // Ah [64*KPAIRS] | Al [64*KPAIRS]
    uint32_t* Ah = sA;
    uint32_t* Al = sA + 64 * KPAIRS;
    const int tid = threadIdx.x, lane = tid & 31, wid = tid >> 5;
    const int mrow0 = bx * 64, ncol0 = by * 128;

    // ---- convert A tile fp32 -> hi/lo fp16 (rn) pairs, XOR-swizzled ----
    #pragma unroll
    for (int c = 0; c < (64 * F4R) / 128; ++c) {
        int idx = tid + c * 128;
        int r = idx / F4R, q = idx % F4R;
        float4 v = *(const float4*)(A + (size_t)(mrow0 + r) * K + q * 4);
        __half hx = __float2half_rn(v.x), hy = __float2half_rn(v.y);
        __half hz = __float2half_rn(v.z), hw = __float2half_rn(v.w);
        __half lx = __float2half_rn(v.x - __half2float(hx));
        __half ly = __float2half_rn(v.y - __half2float(hy));
        __half lz = __float2half_rn(v.z - __half2float(hz));
        __half lw = __float2half_rn(v.w - __half2float(hw));
        uint32_t h01 = pk(__half_as_ushort(hx), __half_as_ushort(hy));
        uint32_t h23 = pk(__half_as_ushort(hz), __half_as_ushort(hw));
        uint32_t l01 = pk(__half_as_ushort(lx), __half_as_ushort(ly));
        uint32_t l23 = pk(__half_as_ushort(lz), __half_as_ushort(lw));
        int p0 = q * 2, sw = (r & 7) << 2, base = r * KPAIRS;
        Ah[base + (p0 ^ sw)]       = h01;
        Ah[base + ((p0 + 1) ^ sw)] = h23;
        Al[base + (p0 ^ sw)]       = l01;
        Al[base + ((p0 + 1) ^ sw)] = l23;
    }
    __syncthreads();

    const int wm = wid & 1, wn = wid >> 1;   // 2 m-warps x 2 n-warps
    const int g = lane >> 2, tg = lane & 3;
    const int NTtot = NTOT >> 3;
    const int ntbase = (ncol0 >> 3) + wn * 8;

    // ldmatrix lane mapping: lanes 0-7 -> rows 0-7 khalf0, 8-15 -> rows 8-15 khalf0,
    // 16-23 -> rows 0-7 khalf1, 24-31 -> rows 8-15 khalf1. Result m0..m3 = a0..a3.
    const int row_in = (lane & 7) | (((lane >> 3) & 1) << 3);
    const int c4 = ((lane >> 4) & 1) << 2;      // pair offset for k-half
    const int swl = (row_in & 7) << 2;          // mt adds 16 rows: (row&7) unchanged
    uint32_t abase[2], lbase[2];
    #pragma unroll
    for (int mt = 0; mt < 2; ++mt) {
        int row = wm * 32 + mt * 16 + row_in;
        abase[mt] = smem_u32(Ah + row * KPAIRS);
        lbase[mt] = smem_u32(Al + row * KPAIRS);
    }

    float acc[2][8][4];
    #pragma unroll
    for (int mt = 0; mt < 2; ++mt)
        #pragma unroll
        for (int nt = 0; nt < 8; ++nt)
            #pragma unroll
            for (int j = 0; j < 4; ++j) acc[mt][nt][j] = 0.f;

    #pragma unroll
    for (int ks = 0; ks < KSTEPS; ++ks) {
        uint32_t poff = (uint32_t)((((ks * 8) | c4) ^ swl) << 2);   // byte offset
        uint32_t ah[2][4], al[2][4];
        LDSM_X4(ah[0], abase[0] + poff);
        LDSM_X4(ah[1], abase[1] + poff);
        LDSM_X4(al[0], lbase[0] + poff);
        LDSM_X4(al[1], lbase[1] + poff);
        #pragma unroll
        for (int nt = 0; nt < 8; ++nt) {
            uint2 b = Bp[(size_t)(ks * NTtot + ntbase + nt) * 32 + lane];
            #pragma unroll
            for (int mt = 0; mt < 2; ++mt) {
                MMA_F16(acc[mt][nt], ah[mt], b.x, b.y);   // hi*B
                MMA_F16(acc[mt][nt], al[mt], b.x, b.y);   // lo*B
            }
        }
    }

    // ---- epilogue: bias (+relu) + store ----
    #pragma unroll
    for (int mt = 0; mt < 2; ++mt) {
        int row = mrow0 + wm * 32 + mt * 16 + g;
        #pragma unroll
        for (int nt = 0; nt < 8; ++nt) {
            int col = ncol0 + wn * 64 + nt * 8 + tg * 2;
            float b0 = bias[col], b1 = bias[col + 1];
            float2 v0 = make_float2(acc[mt][nt][0] + b0, acc[mt][nt][1] + b1);
            float2 v1 = make_float2(acc[mt][nt][2] + b0, acc[mt][nt][3] + b1);
            if (RELU) {
                v0.x = fmaxf(v0.x, 0.f); v0.y = fmaxf(v0.y, 0.f);
                v1.x = fmaxf(v1.x, 0.f); v1.y = fmaxf(v1.y, 0.f);
            }
            *(float2*)(C + (size_t)row * NTOT + col)       = v0;
            *(float2*)(C + (size_t)(row + 8) * NTOT + col) = v1;
        }
    }
}

template<int K, bool RELU>
__global__ __launch_bounds__(128, 4)
void mma_gemm_kernel(const float* __restrict__ A, const uint2* __restrict__ Bp,
                     const float* __restrict__ bias, float* __restrict__ C, int NTOT) {
    gemm_body<K, RELU>(A, Bp, bias, C, NTOT, blockIdx.x, blockIdx.y);
}

// Dual GEMM: two independent same-shape GEMMs in one launch (kills one tail).
template<int K, bool RELU>
__global__ __launch_bounds__(128, 4)
void mma_gemm_dual_kernel(const float* __restrict__ A0, const uint2* __restrict__ B0,
                          const float* __restrict__ c0, float* __restrict__ C0,
                          const float* __restrict__ A1, const uint2* __restrict__ B1,
                          const float* __restrict__ c1, float* __restrict__ C1,
                          int NTOT, int split) {
    int bx = blockIdx.x;
    if (bx < split) gemm_body<K, RELU>(A0, B0, c0, C0, NTOT, bx, blockIdx.y);
    else            gemm_body<K, RELU>(A1, B1, c1, C1, NTOT, bx - split, blockIdx.y);
}

// ======================= adjacency build ========================================
__global__ void build_adj_kernel(const float* __restrict__ mask) {
    int warp = (blockIdx.x * blockDim.x + threadIdx.x) >> 5;
    int lane = threadIdx.x & 31;
    if (warp >= RB) return;
    const float* row = mask + (size_t)warp * NN;
    int cnt = 0;
    for (int j0 = 0; j0 < NN; j0 += 32) {
        int j = j0 + lane;
        bool on = (j < NN) && (row[j] > 0.5f);
        unsigned bal = __ballot_sync(0xffffffffu, on);
        if (on) {
            int pos = cnt + __popc(bal & ((1u << lane) - 1u));
            if (pos < MAXJ) g_adj[warp * MAXJ + pos] = j;
        }
        cnt += __popc(bal);
    }
    if (lane == 0) g_cnt[warp] = min(cnt, MAXJ);
}

// ======================= sparse attention (warp/row, 2-way pipelined) ===========
__global__ void spattn_kernel(const float* __restrict__ vqk, float* __restrict__ out) {
    int warp = (blockIdx.x * blockDim.x + threadIdx.x) >> 5;
    int lane = threadIdx.x & 31;
    if (warp >= RB) return;
    int base = (warp / NN) * NN;
    float4 q4 = *(const float4*)(vqk + (size_t)warp * 384 + 128 + lane * 4);
    int cnt = g_cnt[warp];
    const int* adj = g_adj + warp * MAXJ;
    float m = -3.4e38f, l = 0.f;
    float4 acc = make_float4(0.f, 0.f, 0.f, 0.f);
    int t = 0;
    for (; t + 2 <= cnt; t += 2) {
        int2 jj = *(const int2*)(adj + t);           // 8B-aligned (t even)
        size_t j0 = (size_t)(base + jj.x) * 384;
        size_t j1 = (size_t)(base + jj.y) * 384;
        // issue all 4 gathers up front (MLP=4)
        float4 k0 = *(const float4*)(vqk + j0 + 256 + lane * 4);
        float4 k1 = *(const float4*)(vqk + j1 + 256 + lane * 4);
        float4 v0 = *(const float4*)(vqk + j0 + lane * 4);
        float4 v1 = *(const float4*)(vqk + j1 + lane * 4);
        float p0 = q4.x*k0.x + q4.y*k0.y + q4.z*k0.z + q4.w*k0.w;
        float p1 = q4.x*k1.x + q4.y*k1.y + q4.z*k1.z + q4.w*k1.w;
        // interleaved butterfly reductions (independent chains overlap)
        #pragma unroll
        for (int o = 16; o > 0; o >>= 1) {
            p0 += __shfl_xor_sync(0xffffffffu, p0, o);
            p1 += __shfl_xor_sync(0xffffffffu, p1, o);
        }
        // two sequential online-softmax updates
        {
            float nm = fmaxf(m, p0);
            float sc = __expf(m - nm);
            float e  = __expf(p0 - nm);
            l = l * sc + e;
            acc.x = acc.x * sc + e * v0.x;
            acc.y = acc.y * sc + e * v0.y;
            acc.z = acc.z * sc + e * v0.z;
            acc.w = acc.w * sc + e * v0.w;
            m = nm;
        }
        {
            float nm = fmaxf(m, p1);
            float sc = __expf(m - nm);
            float e  = __expf(p1 - nm);
            l = l * sc + e;
            acc.x = acc.x * sc + e * v1.x;
            acc.y = acc.y * sc + e * v1.y;
            acc.z = acc.z * sc + e * v1.z;
            acc.w = acc.w * sc + e * v1.w;
            m = nm;
        }
    }
    if (t < cnt) {
        size_t j = (size_t)(base + adj[t]) * 384;
        float4 k4 = *(const float4*)(vqk + j + 256 + lane * 4);
        float4 v4 = *(const float4*)(vqk + j + lane * 4);
        float p = q4.x*k4.x + q4.y*k4.y + q4.z*k4.z + q4.w*k4.w;
        #pragma unroll
        for (int o = 16; o > 0; o >>= 1) p += __shfl_xor_sync(0xffffffffu, p, o);
        float nm = fmaxf(m, p);
        float sc = __expf(m - nm);
        float e  = __expf(p - nm);
        l = l * sc + e;
        acc.x = acc.x * sc + e * v4.x;
        acc.y = acc.y * sc + e * v4.y;
        acc.z = acc.z * sc + e * v4.z;
        acc.w = acc.w * sc + e * v4.w;
    }
    float inv = 1.f / l;
    float4 o4 = make_float4(acc.x*inv, acc.y*inv, acc.z*inv, acc.w*inv);
    *(float4*)(out + (size_t)warp * HH + lane * 4) = o4;
}

// ======================= fused GRU gate + FC head (warp/row) ====================
__global__ void gru_fc_kernel(const float* __restrict__ g1, const float* __restrict__ g2,
                              const float* __restrict__ hin, const float* __restrict__ fcW,
                              const float* __restrict__ fcb,
                              float* __restrict__ hout, float* __restrict__ qout) {
    __shared__ float Wt[AA * HH];   // transposed: Wt[a*128 + k]
    __shared__ float bs[AA];
    int tid = threadIdx.x;
    for (int i = tid; i < AA * HH; i += blockDim.x) {
        int k = i / AA, a = i % AA;
        Wt[a * HH + k] = fcW[i];
    }
    if (tid < AA) bs[tid] = fcb[tid];
    __syncthreads();
    int warp = (blockIdx.x * blockDim.x + tid) >> 5;
    int lane = tid & 31;
    if (warp >= RB) return;
    size_t b = (size_t)warp * (3 * HH) + lane * 4;
    float4 xr = *(const float4*)(g1 + b);
    float4 hr = *(const float4*)(g2 + b);
    float4 xz = *(const float4*)(g1 + b + HH);
    float4 hz = *(const float4*)(g2 + b + HH);
    float4 xn = *(const float4*)(g1 + b + 2 * HH);
    float4 hn = *(const float4*)(g2 + b + 2 * HH);
    float4 hi4 = *(const float4*)(hin + (size_t)warp * HH + lane * 4);
    float4 o;
    {
        float r = 1.f / (1.f + __expf(-(xr.x + hr.x)));
        float z = 1.f / (1.f + __expf(-(xz.x + hz.x)));
        float n = tanhf(xn.x + r * hn.x);
        o.x = (1.f - z) * n + z * hi4.x;
    }
    {
        float r = 1.f / (1.f + __expf(-(xr.y + hr.y)));
        float z = 1.f / (1.f + __expf(-(xz.y + hz.y)));
        float n = tanhf(xn.y + r * hn.y);
        o.y = (1.f - z) * n + z * hi4.y;
    }
    {
        float r = 1.f / (1.f + __expf(-(xr.z + hr.z)));
        float z = 1.f / (1.f + __expf(-(xz.z + hz.z)));
        float n = tanhf(xn.z + r * hn.z);
        o.z = (1.f - z) * n + z * hi4.z;
    }
    {
        float r = 1.f / (1.f + __expf(-(xr.w + hr.w)));
        float z = 1.f / (1.f + __expf(-(xz.w + hz.w)));
        float n = tanhf(xn.w + r * hn.w);
        o.w = (1.f - z) * n + z * hi4.w;
    }
    *(float4*)(hout + (size_t)warp * HH + lane * 4) = o;
    #pragma unroll
    for (int a = 0; a < AA; ++a) {
        float4 w4 = *(const float4*)(Wt + a * HH + lane * 4);
        float p = o.x*w4.x + o.y*w4.y + o.z*w4.z + o.w*w4.w;
        #pragma unroll
        for (int off = 16; off > 0; off >>= 1) p += __shfl_xor_sync(0xffffffffu, p, off);
        if (lane == 0) qout[warp * AA + a] = p + bs[a];
    }
}

// ======================= launch =================================================
extern "C" void kernel_launch(void* const* d_in, const int* in_sizes, int n_in,
                              void* d_out, int out_size) {
    const float* x      = (const float*)d_in[0];
    const float* mask   = (const float*)d_in[1];
    const float* hidden = (const float*)d_in[2];
    const float* encW   = (const float*)d_in[3];
    const float* encb   = (const float*)d_in[4];
    const float* Wv1 = (const float*)d_in[5],  *bv1 = (const float*)d_in[6];
    const float* Wk1 = (const float*)d_in[7],  *bk1 = (const float*)d_in[8];
    const float* Wq1 = (const float*)d_in[9],  *bq1 = (const float*)d_in[10];
    const float* Wo1 = (const float*)d_in[11], *bo1 = (const float*)d_in[12];
    const float* Wv2 = (const float*)d_in[13], *bv2 = (const float*)d_in[14];
    const float* Wk2 = (const float*)d_in[15], *bk2 = (const float*)d_in[16];
    const float* Wq2 = (const float*)d_in[17], *bq2 = (const float*)d_in[18];
    const float* Wo2 = (const float*)d_in[19], *bo2 = (const float*)d_in[20];
    const float* Wih = (const float*)d_in[21], *bih = (const float*)d_in[22];
    const float* Whh = (const float*)d_in[23], *bhh = (const float*)d_in[24];
    const float* fcW = (const float*)d_in[25], *fcb = (const float*)d_in[26];

    float* out = (float*)d_out;
    float* qout = out;
    float* hout = out + (size_t)RB * AA;

    float *ph, *pt, *pg1, *pg2, *pbp1, *pbp2;
    uint2 *pBenc, *pBo1, *pBo2, *pBih, *pBhh, *pBv1, *pBv2;
    cudaGetSymbolAddress((void**)&ph,   g_h);
    cudaGetSymbolAddress((void**)&pt,   g_t);
    cudaGetSymbolAddress((void**)&pg1,  g_g1);
    cudaGetSymbolAddress((void**)&pg2,  g_g2);
    cudaGetSymbolAddress((void**)&pBenc, g_Benc);
    cudaGetSymbolAddress((void**)&pBo1,  g_Bo1);
    cudaGetSymbolAddress((void**)&pBo2,  g_Bo2);
    cudaGetSymbolAddress((void**)&pBih,  g_Bih);
    cudaGetSymbolAddress((void**)&pBhh,  g_Bhh);
    cudaGetSymbolAddress((void**)&pBv1,  g_Bv1);
    cudaGetSymbolAddress((void**)&pBv2,  g_Bv2);
    cudaGetSymbolAddress((void**)&pbp1,  g_bp1);
    cudaGetSymbolAddress((void**)&pbp2,  g_bp2);

    const int WB = 256;
    const int WG = 128;                       // GEMM block size (4 warps)
    const int rowBlocks = RB / (WB / 32);     // 4000
    const int smemK128 = 64 * 64 * 4 * 2;     // 32 KB
    const int smemK64  = 64 * 32 * 4 * 2;     // 16 KB

    cudaFuncSetAttribute(mma_gemm_kernel<64,  true>,  cudaFuncAttributeMaxDynamicSharedMemorySize, smemK64);
    cudaFuncSetAttribute(mma_gemm_kernel<128, true>,  cudaFuncAttributeMaxDynamicSharedMemorySize, smemK128);
    cudaFuncSetAttribute(mma_gemm_dual_kernel<128, false>, cudaFuncAttributeMaxDynamicSharedMemorySize, smemK128);

    // ---- merged weight packing (single launch) + adjacency ----
    pack_all_kernel<<<(59648 + WB - 1) / WB, WB>>>(
        encW, Wo1, Wo2, Wih, Whh,
        Wv1, Wq1, Wk1, Wv2, Wq2, Wk2,
        bv1, bq1, bk1, bv2, bq2, bk2,
        pBenc, pBo1, pBo2, pBih, pBhh, pBv1, pBv2, pbp1, pbp2);
    build_adj_kernel<<<rowBlocks, WB>>>(mask);

    dim3 grid128(RB / 64, 1);    // (500,1)
    dim3 grid384(RB / 64, 3);    // (500,3)
    dim3 gridDual(2 * RB / 64, 3);  // (1000,3)

    // encoder: h1 = relu(x @ encW + encb)
    mma_gemm_kernel<64, true><<<grid128, WG, smemK64>>>(x, pBenc, encb, ph, HH);

    // ---- attention layer 1 ----
    mma_gemm_kernel<128, true><<<grid384, WG, smemK128>>>(ph, pBv1, pbp1, pg1, 3*HH);
    spattn_kernel<<<rowBlocks, WB>>>(pg1, pt);
    mma_gemm_kernel<128, true><<<grid128, WG, smemK128>>>(pt, pBo1, bo1, ph, HH);

    // ---- attention layer 2 ----
    mma_gemm_kernel<128, true><<<grid384, WG, smemK128>>>(ph, pBv2, pbp2, pg1, 3*HH);
    spattn_kernel<<<rowBlocks, WB>>>(pg1, pt);
    mma_gemm_kernel<128, true><<<grid128, WG, smemK128>>>(pt, pBo2, bo2, ph, HH);

    // ---- GRU GEMMs (merged into one launch) + fused gate/head ----
    mma_gemm_dual_kernel<128, false><<<gridDual, WG, smemK128>>>(
        ph, pBih, bih, pg1, hidden, pBhh, bhh, pg2, 3*HH, RB / 64);
    gru_fc_kernel<<<rowBlocks, WB>>>(pg1, pg2, hidden, fcW, fcb, hout, qout);

    (void)in_sizes; (void)n_in; (void)out_size;
}

// round 17
// speedup vs baseline: 1.4309x; 1.0392x over previous
#include <cuda_runtime.h>
#include <cuda_fp16.h>
#include <cstdint>

// Problem constants
#define BB   32
#define NN   1000
#define DIN  64
#define HH   128
#define AA   10
#define RB   (BB*NN)          // 32000 rows
#define MAXJ 128

// ======================= scratch (static device globals) ========================
__device__ float g_h  [RB*HH];
__device__ float g_t  [RB*HH];
__device__ float g_g1 [RB*3*HH];
__device__ float g_g2 [RB*3*HH];
__device__ int   g_adj[RB*MAXJ];
__device__ int   g_cnt[RB];
// fragment-packed fp16 weights, PAIR-PACKED: uint4 per (kstep, ntpair, lane)
// = {b(nt0).x, b(nt0).y, b(nt1).x, b(nt1).y}; stored as uint2 elements.
__device__ uint2 g_Benc[4*16*32];      // K=64,  N=128
__device__ uint2 g_Bo1 [8*16*32];      // K=128, N=128
__device__ uint2 g_Bo2 [8*16*32];
__device__ uint2 g_Bih [8*48*32];      // K=128, N=384
__device__ uint2 g_Bhh [8*48*32];
__device__ uint2 g_Bv1 [8*48*32];
__device__ uint2 g_Bv2 [8*48*32];
__device__ float g_bp1 [3*HH];
__device__ float g_bp2 [3*HH];

// ======================= helpers ================================================
__device__ __forceinline__ uint32_t smem_u32(const void* p) {
    uint32_t a;
    asm("{ .reg .u64 t; cvta.to.shared.u64 t, %1; cvt.u32.u64 %0, t; }" : "=r"(a) : "l"(p));
    return a;
}
__device__ __forceinline__ uint32_t pk(uint16_t lo, uint16_t hi) {
    return ((uint32_t)hi << 16) | lo;
}
#define MMA_F16(d, a, b0, b1)                                                    \
    asm volatile("mma.sync.aligned.m16n8k16.row.col.f32.f16.f16.f32 "            \
                 "{%0,%1,%2,%3}, {%4,%5,%6,%7}, {%8,%9}, {%0,%1,%2,%3};"         \
                 : "+f"((d)[0]), "+f"((d)[1]), "+f"((d)[2]), "+f"((d)[3])        \
                 : "r"((a)[0]), "r"((a)[1]), "r"((a)[2]), "r"((a)[3]),           \
                   "r"(b0), "r"(b1))
#define LDSM_X4(r, addr)                                                         \
    asm volatile("ldmatrix.sync.aligned.m8n8.x4.shared.b16 {%0,%1,%2,%3}, [%4];" \
                 : "=r"((r)[0]), "=r"((r)[1]), "=r"((r)[2]), "=r"((r)[3])        \
                 : "r"(addr))

// ======================= merged weight packing (fp16 rn, pair-packed) ===========
// Logical fragment (ks, ntg, lane) holds uint2 {b01, b23} for ntile ntg.
// Pair-packed output index (in uint2 units):
//   out = (((ks*(NT/2) + (ntg>>1))*32 + lane) << 1) | (ntg & 1)
// so a uint4 load at (ks*(NT/2)+ntp)*32+lane yields ntiles {2*ntp, 2*ntp+1}.
__device__ __forceinline__ void pack_one(const float* __restrict__ W,
                                         uint2* __restrict__ Bp,
                                         int N, int K, int transb, int i) {
    int NT = N >> 3;
    int lane = i & 31, rest = i >> 5;
    int ntg = rest % NT, ks = rest / NT;
    int n = ntg * 8 + (lane >> 2);
    int k0 = ks * 16 + (lane & 3) * 2;
    uint16_t h[4];
    #pragma unroll
    for (int j = 0; j < 4; ++j) {
        int k = k0 + (j >> 1) * 8 + (j & 1);
        float v = transb ? W[n * K + k] : W[k * N + n];
        h[j] = __half_as_ushort(__float2half_rn(v));
    }
    int out = ((((ks * (NT >> 1) + (ntg >> 1)) * 32 + lane) << 1) | (ntg & 1));
    Bp[out] = make_uint2(pk(h[0], h[1]), pk(h[2], h[3]));
}
__device__ __forceinline__ void pack_one_vqk(const float* __restrict__ Wv,
                                             const float* __restrict__ Wq,
                                             const float* __restrict__ Wk,
                                             uint2* __restrict__ Bp, int i) {
    const int NT = 48, K = 128;
    int lane = i & 31, rest = i >> 5;
    int ntg = rest % NT, ks = rest / NT;
    int n = ntg * 8 + (lane >> 2);
    const float* W = (n < 128) ? Wv : (n < 256) ? Wq : Wk;
    int nn = n & 127;
    int k0 = ks * 16 + (lane & 3) * 2;
    uint16_t h[4];
    #pragma unroll
    for (int j = 0; j < 4; ++j) {
        int k = k0 + (j >> 1) * 8 + (j & 1);
        h[j] = __half_as_ushort(__float2half_rn(W[k * K + nn]));
    }
    int out = ((((ks * (NT >> 1) + (ntg >> 1)) * 32 + lane) << 1) | (ntg & 1));
    Bp[out] = make_uint2(pk(h[0], h[1]), pk(h[2], h[3]));
}

__global__ void pack_all_kernel(
    const float* encW, const float* Wo1, const float* Wo2,
    const float* Wih,  const float* Whh,
    const float* Wv1, const float* Wq1, const float* Wk1,
    const float* Wv2, const float* Wq2, const float* Wk2,
    const float* bv1, const float* bq1, const float* bk1,
    const float* bv2, const float* bq2, const float* bk2,
    uint2* Benc, uint2* Bo1, uint2* Bo2, uint2* Bih, uint2* Bhh,
    uint2* Bv1, uint2* Bv2, float* bp1, float* bp2) {
    int i = blockIdx.x * blockDim.x + threadIdx.x;
    if      (i < 2048)  pack_one(encW, Benc, 128, 64, 0, i);
    else if (i < 6144)  pack_one(Wo1, Bo1, 128, 128, 0, i - 2048);
    else if (i < 10240) pack_one(Wo2, Bo2, 128, 128, 0, i - 6144);
    else if (i < 22528) pack_one(Wih, Bih, 384, 128, 1, i - 10240);
    else if (i < 34816) pack_one(Whh, Bhh, 384, 128, 1, i - 22528);
    else if (i < 47104) pack_one_vqk(Wv1, Wq1, Wk1, Bv1, i - 34816);
    else if (i < 59392) pack_one_vqk(Wv2, Wq2, Wk2, Bv2, i - 47104);
    else if (i < 59520) { int j = i - 59392; bp1[j] = bv1[j]; bp1[128+j] = bq1[j]; bp1[256+j] = bk1[j]; }
    else if (i < 59648) { int j = i - 59520; bp2[j] = bv2[j]; bp2[128+j] = bq2[j]; bp2[256+j] = bk2[j]; }
}

// ======================= fp16 2-term tensor-core GEMM ===========================
// C[32000, NTOT] = relu?(A[32000,K] x B + bias), B = f16_rn(W), pair-packed.
// A = Ah + Al (fp16 rn split); D = Ah*B + Al*B.
// CTA tile 64x128, 4 warps (128 thr) = 2m x 2n, warp tile 32x64 (2mt x 8nt).
template<int K, bool RELU>
__device__ __forceinline__ void gemm_body(const float* __restrict__ A,
                                          const uint2* __restrict__ Bp,
                                          const float* __restrict__ bias,
                                          float* __restrict__ C,
                                          int NTOT, int bx, int by) {
    constexpr int KSTEPS = K / 16, KPAIRS = K / 2, F4R = K / 4;
    extern __shared__ uint32_t sA[];                  // Ah [64*KPAIRS] | Al [64*KPAIRS]
    uint32_t* Ah = sA;
    uint32_t* Al = sA + 64 * KPAIRS;
    const int tid = threadIdx.x, lane = tid & 31, wid = tid >> 5;
    const int mrow0 = bx * 64, ncol0 = by * 128;

    // ---- convert A tile fp32 -> hi/lo fp16 (rn) pairs, XOR-swizzled ----
    #pragma unroll
    for (int c = 0; c < (64 * F4R) / 128; ++c) {
        int idx = tid + c * 128;
        int r = idx / F4R, q = idx % F4R;
        float4 v = *(const float4*)(A + (size_t)(mrow0 + r) * K + q * 4);
        __half hx = __float2half_rn(v.x), hy = __float2half_rn(v.y);
        __half hz = __float2half_rn(v.z), hw = __float2half_rn(v.w);
        __half lx = __float2half_rn(v.x - __half2float(hx));
        __half ly = __float2half_rn(v.y - __half2float(hy));
        __half lz = __float2half_rn(v.z - __half2float(hz));
        __half lw = __float2half_rn(v.w - __half2float(hw));
        uint32_t h01 = pk(__half_as_ushort(hx), __half_as_ushort(hy));
        uint32_t h23 = pk(__half_as_ushort(hz), __half_as_ushort(hw));
        uint32_t l01 = pk(__half_as_ushort(lx), __half_as_ushort(ly));
        uint32_t l23 = pk(__half_as_ushort(lz), __half_as_ushort(lw));
        int p0 = q * 2, sw = (r & 7) << 2, base = r * KPAIRS;
        Ah[base + (p0 ^ sw)]       = h01;
        Ah[base + ((p0 + 1) ^ sw)] = h23;
        Al[base + (p0 ^ sw)]       = l01;
        Al[base + ((p0 + 1) ^ sw)] = l23;
    }
    __syncthreads();

    const int wm = wid & 1, wn = wid >> 1;   // 2 m-warps x 2 n-warps
    const int g = lane >> 2, tg = lane & 3;
    const int NT2 = NTOT >> 4;               // n-tile pairs total
    const int ntb2 = (ncol0 >> 4) + wn * 4;  // this warp's first ntile pair

    // ldmatrix lane mapping: lanes 0-7 -> rows 0-7 khalf0, 8-15 -> rows 8-15 khalf0,
    // 16-23 -> rows 0-7 khalf1, 24-31 -> rows 8-15 khalf1. Result m0..m3 = a0..a3.
    const int row_in = (lane & 7) | (((lane >> 3) & 1) << 3);
    const int c4 = ((lane >> 4) & 1) << 2;      // pair offset for k-half
    const int swl = (row_in & 7) << 2;          // mt adds 16 rows: (row&7) unchanged
    uint32_t abase[2], lbase[2];
    #pragma unroll
    for (int mt = 0; mt < 2; ++mt) {
        int row = wm * 32 + mt * 16 + row_in;
        abase[mt] = smem_u32(Ah + row * KPAIRS);
        lbase[mt] = smem_u32(Al + row * KPAIRS);
    }

    float acc[2][8][4];
    #pragma unroll
    for (int mt = 0; mt < 2; ++mt)
        #pragma unroll
        for (int nt = 0; nt < 8; ++nt)
            #pragma unroll
            for (int j = 0; j < 4; ++j) acc[mt][nt][j] = 0.f;

    #pragma unroll
    for (int ks = 0; ks < KSTEPS; ++ks) {
        uint32_t poff = (uint32_t)((((ks * 8) | c4) ^ swl) << 2);   // byte offset
        uint32_t ah[2][4], al[2][4];
        LDSM_X4(ah[0], abase[0] + poff);
        LDSM_X4(ah[1], abase[1] + poff);
        LDSM_X4(al[0], lbase[0] + poff);
        LDSM_X4(al[1], lbase[1] + poff);
        #pragma unroll
        for (int ntp = 0; ntp < 4; ++ntp) {
            uint4 bb = *((const uint4*)Bp + (size_t)(ks * NT2 + ntb2 + ntp) * 32 + lane);
            #pragma unroll
            for (int mt = 0; mt < 2; ++mt) {
                MMA_F16(acc[mt][2*ntp],   ah[mt], bb.x, bb.y);   // hi*B, nt even
                MMA_F16(acc[mt][2*ntp],   al[mt], bb.x, bb.y);   // lo*B
                MMA_F16(acc[mt][2*ntp+1], ah[mt], bb.z, bb.w);   // hi*B, nt odd
                MMA_F16(acc[mt][2*ntp+1], al[mt], bb.z, bb.w);   // lo*B
            }
        }
    }

    // ---- epilogue: bias (+relu) + store ----
    #pragma unroll
    for (int mt = 0; mt < 2; ++mt) {
        int row = mrow0 + wm * 32 + mt * 16 + g;
        #pragma unroll
        for (int nt = 0; nt < 8; ++nt) {
            int col = ncol0 + wn * 64 + nt * 8 + tg * 2;
            float b0 = bias[col], b1 = bias[col + 1];
            float2 v0 = make_float2(acc[mt][nt][0] + b0, acc[mt][nt][1] + b1);
            float2 v1 = make_float2(acc[mt][nt][2] + b0, acc[mt][nt][3] + b1);
            if (RELU) {
                v0.x = fmaxf(v0.x, 0.f); v0.y = fmaxf(v0.y, 0.f);
                v1.x = fmaxf(v1.x, 0.f); v1.y = fmaxf(v1.y, 0.f);
            }
            *(float2*)(C + (size_t)row * NTOT + col)       = v0;
            *(float2*)(C + (size_t)(row + 8) * NTOT + col) = v1;
        }
    }
}

template<int K, bool RELU>
__global__ __launch_bounds__(128, 4)
void mma_gemm_kernel(const float* __restrict__ A, const uint2* __restrict__ Bp,
                     const float* __restrict__ bias, float* __restrict__ C, int NTOT) {
    gemm_body<K, RELU>(A, Bp, bias, C, NTOT, blockIdx.x, blockIdx.y);
}

// Dual GEMM: two independent same-shape GEMMs in one launch (kills one tail).
template<int K, bool RELU>
__global__ __launch_bounds__(128, 4)
void mma_gemm_dual_kernel(const float* __restrict__ A0, const uint2* __restrict__ B0,
                          const float* __restrict__ c0, float* __restrict__ C0,
                          const float* __restrict__ A1, const uint2* __restrict__ B1,
                          const float* __restrict__ c1, float* __restrict__ C1,
                          int NTOT, int split) {
    int bx = blockIdx.x;
    if (bx < split) gemm_body<K, RELU>(A0, B0, c0, C0, NTOT, bx, blockIdx.y);
    else            gemm_body<K, RELU>(A1, B1, c1, C1, NTOT, bx - split, blockIdx.y);
}

// ======================= adjacency build ========================================
__global__ void build_adj_kernel(const float* __restrict__ mask) {
    int warp = (blockIdx.x * blockDim.x + threadIdx.x) >> 5;
    int lane = threadIdx.x & 31;
    if (warp >= RB) return;
    const float* row = mask + (size_t)warp * NN;
    int cnt = 0;
    for (int j0 = 0; j0 < NN; j0 += 32) {
        int j = j0 + lane;
        bool on = (j < NN) && (row[j] > 0.5f);
        unsigned bal = __ballot_sync(0xffffffffu, on);
        if (on) {
            int pos = cnt + __popc(bal & ((1u << lane) - 1u));
            if (pos < MAXJ) g_adj[warp * MAXJ + pos] = j;
        }
        cnt += __popc(bal);
    }
    if (lane == 0) g_cnt[warp] = min(cnt, MAXJ);
}

// ======================= sparse attention (warp/row, SW-pipelined pairs) ========
__global__ void spattn_kernel(const float* __restrict__ vqk, float* __restrict__ out) {
    int warp = (blockIdx.x * blockDim.x + threadIdx.x) >> 5;
    int lane = threadIdx.x & 31;
    if (warp >= RB) return;
    int base = (warp / NN) * NN;
    float4 q4 = *(const float4*)(vqk + (size_t)warp * 384 + 128 + lane * 4);
    int cnt = g_cnt[warp];                       // >= 1 (self-loop)
    const int* adj = g_adj + warp * MAXJ;
    float m = -3.4e38f, l = 0.f;
    float4 acc = make_float4(0.f, 0.f, 0.f, 0.f);
    int npair = (cnt + 1) >> 1;
    // prologue: load pair 0 (pad odd with duplicate; neutralized via p1=-inf)
    int a0 = adj[0];
    int a1 = (cnt > 1) ? adj[1] : a0;
    size_t j0 = (size_t)(base + a0) * 384;
    size_t j1 = (size_t)(base + a1) * 384;
    float4 k0 = *(const float4*)(vqk + j0 + 256 + lane * 4);
    float4 k1 = *(const float4*)(vqk + j1 + 256 + lane * 4);
    float4 v0 = *(const float4*)(vqk + j0 + lane * 4);
    float4 v1 = *(const float4*)(vqk + j1 + lane * 4);
    for (int pp = 0; pp < npair; ++pp) {
        float4 ck0 = k0, ck1 = k1, cv0 = v0, cv1 = v1;
        bool ok1 = (2 * pp + 1 < cnt);
        // prefetch next pair while we reduce the current one
        int tn = 2 * pp + 2;
        if (tn < cnt) {
            int b0i = adj[tn];
            int b1i = (tn + 1 < cnt) ? adj[tn + 1] : b0i;
            j0 = (size_t)(base + b0i) * 384;
            j1 = (size_t)(base + b1i) * 384;
            k0 = *(const float4*)(vqk + j0 + 256 + lane * 4);
            k1 = *(const float4*)(vqk + j1 + 256 + lane * 4);
            v0 = *(const float4*)(vqk + j0 + lane * 4);
            v1 = *(const float4*)(vqk + j1 + lane * 4);
        }
        float p0 = q4.x*ck0.x + q4.y*ck0.y + q4.z*ck0.z + q4.w*ck0.w;
        float p1 = q4.x*ck1.x + q4.y*ck1.y + q4.z*ck1.z + q4.w*ck1.w;
        #pragma unroll
        for (int o = 16; o > 0; o >>= 1) {
            p0 += __shfl_xor_sync(0xffffffffu, p0, o);
            p1 += __shfl_xor_sync(0xffffffffu, p1, o);
        }
        if (!ok1) p1 = -3.4e38f;                  // padded slot -> e=0, sc=1
        {
            float nm = fmaxf(m, p0);
            float sc = __expf(m - nm);
            float e  = __expf(p0 - nm);
            l = l * sc + e;
            acc.x = acc.x * sc + e * cv0.x;
            acc.y = acc.y * sc + e * cv0.y;
            acc.z = acc.z * sc + e * cv0.z;
            acc.w = acc.w * sc + e * cv0.w;
            m = nm;
        }
        {
            float nm = fmaxf(m, p1);
            float sc = __expf(m - nm);
            float e  = __expf(p1 - nm);
            l = l * sc + e;
            acc.x = acc.x * sc + e * cv1.x;
            acc.y = acc.y * sc + e * cv1.y;
            acc.z = acc.z * sc + e * cv1.z;
            acc.w = acc.w * sc + e * cv1.w;
            m = nm;
        }
    }
    float inv = 1.f / l;
    float4 o4 = make_float4(acc.x*inv, acc.y*inv, acc.z*inv, acc.w*inv);
    *(float4*)(out + (size_t)warp * HH + lane * 4) = o4;
}

// ======================= fused GRU gate + FC head (warp/row) ====================
__global__ void gru_fc_kernel(const float* __restrict__ g1, const float* __restrict__ g2,
                              const float* __restrict__ hin, const float* __restrict__ fcW,
                              const float* __restrict__ fcb,
                              float* __restrict__ hout, float* __restrict__ qout) {
    __shared__ float Wt[AA * HH];   // transposed: Wt[a*128 + k]
    __shared__ float bs[AA];
    int tid = threadIdx.x;
    for (int i = tid; i < AA * HH; i += blockDim.x) {
        int k = i / AA, a = i % AA;
        Wt[a * HH + k] = fcW[i];
    }
    if (tid < AA) bs[tid] = fcb[tid];
    __syncthreads();
    int warp = (blockIdx.x * blockDim.x + tid) >> 5;
    int lane = tid & 31;
    if (warp >= RB) return;
    size_t b = (size_t)warp * (3 * HH) + lane * 4;
    float4 xr = *(const float4*)(g1 + b);
    float4 hr = *(const float4*)(g2 + b);
    float4 xz = *(const float4*)(g1 + b + HH);
    float4 hz = *(const float4*)(g2 + b + HH);
    float4 xn = *(const float4*)(g1 + b + 2 * HH);
    float4 hn = *(const float4*)(g2 + b + 2 * HH);
    float4 hi4 = *(const float4*)(hin + (size_t)warp * HH + lane * 4);
    float4 o;
    {
        float r = 1.f / (1.f + __expf(-(xr.x + hr.x)));
        float z = 1.f / (1.f + __expf(-(xz.x + hz.x)));
        float n = tanhf(xn.x + r * hn.x);
        o.x = (1.f - z) * n + z * hi4.x;
    }
    {
        float r = 1.f / (1.f + __expf(-(xr.y + hr.y)));
        float z = 1.f / (1.f + __expf(-(xz.y + hz.y)));
        float n = tanhf(xn.y + r * hn.y);
        o.y = (1.f - z) * n + z * hi4.y;
    }
    {
        float r = 1.f / (1.f + __expf(-(xr.z + hr.z)));
        float z = 1.f / (1.f + __expf(-(xz.z + hz.z)));
        float n = tanhf(xn.z + r * hn.z);
        o.z = (1.f - z) * n + z * hi4.z;
    }
    {
        float r = 1.f / (1.f + __expf(-(xr.w + hr.w)));
        float z = 1.f / (1.f + __expf(-(xz.w + hz.w)));
        float n = tanhf(xn.w + r * hn.w);
        o.w = (1.f - z) * n + z * hi4.w;
    }
    *(float4*)(hout + (size_t)warp * HH + lane * 4) = o;
    #pragma unroll
    for (int a = 0; a < AA; ++a) {
        float4 w4 = *(const float4*)(Wt + a * HH + lane * 4);
        float p = o.x*w4.x + o.y*w4.y + o.z*w4.z + o.w*w4.w;
        #pragma unroll
        for (int off = 16; off > 0; off >>= 1) p += __shfl_xor_sync(0xffffffffu, p, off);
        if (lane == 0) qout[warp * AA + a] = p + bs[a];
    }
}

// ======================= launch =================================================
extern "C" void kernel_launch(void* const* d_in, const int* in_sizes, int n_in,
                              void* d_out, int out_size) {
    const float* x      = (const float*)d_in[0];
    const float* mask   = (const float*)d_in[1];
    const float* hidden = (const float*)d_in[2];
    const float* encW   = (const float*)d_in[3];
    const float* encb   = (const float*)d_in[4];
    const float* Wv1 = (const float*)d_in[5],  *bv1 = (const float*)d_in[6];
    const float* Wk1 = (const float*)d_in[7],  *bk1 = (const float*)d_in[8];
    const float* Wq1 = (const float*)d_in[9],  *bq1 = (const float*)d_in[10];
    const float* Wo1 = (const float*)d_in[11], *bo1 = (const float*)d_in[12];
    const float* Wv2 = (const float*)d_in[13], *bv2 = (const float*)d_in[14];
    const float* Wk2 = (const float*)d_in[15], *bk2 = (const float*)d_in[16];
    const float* Wq2 = (const float*)d_in[17], *bq2 = (const float*)d_in[18];
    const float* Wo2 = (const float*)d_in[19], *bo2 = (const float*)d_in[20];
    const float* Wih = (const float*)d_in[21], *bih = (const float*)d_in[22];
    const float* Whh = (const float*)d_in[23], *bhh = (const float*)d_in[24];
    const float* fcW = (const float*)d_in[25], *fcb = (const float*)d_in[26];

    float* out = (float*)d_out;
    float* qout = out;
    float* hout = out + (size_t)RB * AA;

    float *ph, *pt, *pg1, *pg2, *pbp1, *pbp2;
    uint2 *pBenc, *pBo1, *pBo2, *pBih, *pBhh, *pBv1, *pBv2;
    cudaGetSymbolAddress((void**)&ph,   g_h);
    cudaGetSymbolAddress((void**)&pt,   g_t);
    cudaGetSymbolAddress((void**)&pg1,  g_g1);
    cudaGetSymbolAddress((void**)&pg2,  g_g2);
    cudaGetSymbolAddress((void**)&pBenc, g_Benc);
    cudaGetSymbolAddress((void**)&pBo1,  g_Bo1);
    cudaGetSymbolAddress((void**)&pBo2,  g_Bo2);
    cudaGetSymbolAddress((void**)&pBih,  g_Bih);
    cudaGetSymbolAddress((void**)&pBhh,  g_Bhh);
    cudaGetSymbolAddress((void**)&pBv1,  g_Bv1);
    cudaGetSymbolAddress((void**)&pBv2,  g_Bv2);
    cudaGetSymbolAddress((void**)&pbp1,  g_bp1);
    cudaGetSymbolAddress((void**)&pbp2,  g_bp2);

    const int WB = 256;
    const int WG = 128;                       // GEMM block size (4 warps)
    const int rowBlocks = RB / (WB / 32);     // 4000
    const int smemK128 = 64 * 64 * 4 * 2;     // 32 KB
    const int smemK64  = 64 * 32 * 4 * 2;     // 16 KB

    cudaFuncSetAttribute(mma_gemm_kernel<64,  true>,  cudaFuncAttributeMaxDynamicSharedMemorySize, smemK64);
    cudaFuncSetAttribute(mma_gemm_kernel<128, true>,  cudaFuncAttributeMaxDynamicSharedMemorySize, smemK128);
    cudaFuncSetAttribute(mma_gemm_dual_kernel<128, false>, cudaFuncAttributeMaxDynamicSharedMemorySize, smemK128);

    // ---- merged weight packing (single launch) + adjacency ----
    pack_all_kernel<<<(59648 + WB - 1) / WB, WB>>>(
        encW, Wo1, Wo2, Wih, Whh,
        Wv1, Wq1, Wk1, Wv2, Wq2, Wk2,
        bv1, bq1, bk1, bv2, bq2, bk2,
        pBenc, pBo1, pBo2, pBih, pBhh, pBv1, pBv2, pbp1, pbp2);
    build_adj_kernel<<<rowBlocks, WB>>>(mask);

    dim3 grid128(RB / 64, 1);    // (500,1)
    dim3 grid384(RB / 64, 3);    // (500,3)
    dim3 gridDual(2 * RB / 64, 3);  // (1000,3)

    // encoder: h1 = relu(x @ encW + encb)
    mma_gemm_kernel<64, true><<<grid128, WG, smemK64>>>(x, pBenc, encb, ph, HH);

    // ---- attention layer 1 ----
    mma_gemm_kernel<128, true><<<grid384, WG, smemK128>>>(ph, pBv1, pbp1, pg1, 3*HH);
    spattn_kernel<<<rowBlocks, WB>>>(pg1, pt);
    mma_gemm_kernel<128, true><<<grid128, WG, smemK128>>>(pt, pBo1, bo1, ph, HH);

    // ---- attention layer 2 ----
    mma_gemm_kernel<128, true><<<grid384, WG, smemK128>>>(ph, pBv2, pbp2, pg1, 3*HH);
    spattn_kernel<<<rowBlocks, WB>>>(pg1, pt);
    mma_gemm_kernel<128, true><<<grid128, WG, smemK128>>>(pt, pBo2, bo2, ph, HH);

    // ---- GRU GEMMs (merged into one launch) + fused gate/head ----
    mma_gemm_dual_kernel<128, false><<<gridDual, WG, smemK128>>>(
        ph, pBih, bih, pg1, hidden, pBhh, bhh, pg2, 3*HH, RB / 64);
    gru_fc_kernel<<<rowBlocks, WB>>>(pg1, pg2, hidden, fcW, fcb, hout, qout);

    (void)in_sizes; (void)n_in; (void)out_size;
}